// round 1
// baseline (speedup 1.0000x reference)
#include <cuda_runtime.h>
#include <math.h>

// ---------------- problem constants ----------------
#define BSZ 8
#define SEQ 512
#define ROWS 4096          // BSZ*SEQ
#define SPATIAL 512
#define NF 257             // rfft bins
#define F2 514
#define F4 1028
#define FH 128             // F//2
#define MAX_STEPS 20
#define TOLV 1e-3f

// ---------------- device scratch (static, no allocation) ----------------
__device__ float g_ct[ROWS * F4];     // [c | t] interleaved columns: 0..513 = c, 514..1027 = t
__device__ float g_new[ROWS * F4];
__device__ float g_h[ROWS * F4];      // freq-net hidden (reused c then t)
__device__ float g_fc[ROWS * F2];
__device__ float g_ft[ROWS * F2];
__device__ float g_hdc[ROWS * NF];
__device__ float g_hdt[ROWS * NF];
__device__ float g_hs[ROWS * FH];
__device__ float g_alpha_c[ROWS];
__device__ float g_alpha_t[ROWS];
__device__ float g_gamma[ROWS];
__device__ float g_base_c[BSZ * F4];
__device__ float g_base_t[BSZ * F4];
__device__ float g_rn_c[ROWS], g_rn_t[ROWS], g_sq_c[ROWS], g_sq_t[ROWS];
__device__ float g_scal[4];           // [0]=scale_c [1]=scale_t [2]=apply_enable
__device__ int   g_done;
__device__ float g_Br[SPATIAL * F2];  // rfft matrix  [n][2k | 2k+1]
__device__ float g_Bi[F2 * SPATIAL];  // irfft matrix [2k|2k+1][n]

// ---------------- device helpers ----------------
__device__ __forceinline__ float gelu_f(float x) {
    return 0.5f * x * (1.0f + erff(x * 0.70710678118654752f));
}
__device__ __forceinline__ float sanitize_f(float v) {
    if (isnan(v)) return 0.0f;
    if (isinf(v)) return v > 0.f ? 1e6f : -1e6f;
    return v;
}

// ---------------- table init (also resets done flag) ----------------
__global__ void k_init_tables() {
    int idx = blockIdx.x * blockDim.x + threadIdx.x;
    if (idx == 0) g_done = 0;
    int total = SPATIAL * NF;
    if (idx >= total) return;
    int n = idx / NF, k = idx % NF;
    double r = (double)((k * n) & 511) / 256.0;  // (k*n mod 512)/256 -> theta/pi
    double sv, cv;
    sincospi(r, &sv, &cv);
    // rfft: X_k = sum x_n (cos - i sin)
    g_Br[n * F2 + 2 * k]     = (float)cv;
    g_Br[n * F2 + 2 * k + 1] = (float)(-sv);
    // irfft: x_n = (1/512)[Re0 + (-1)^n Re_{256} + 2 sum_{k=1..255}(Re cos - Im sin)]
    double w = (k == 0 || k == NF - 1) ? 1.0 : 2.0;
    g_Bi[(2 * k) * SPATIAL + n]     = (float)(w * cv / 512.0);
    g_Bi[(2 * k + 1) * SPATIAL + n] = (float)(-w * sv / 512.0);  // exactly 0 at k=0,256
}

// ---------------- generic SGEMM: C = act(A@B + bias[col] + base[batch][col]) ----------------
// 128x128 tile, 8x8 per thread, 256 threads, BK=8
__global__ void k_gemm(const float* __restrict__ A, int lda,
                       const float* __restrict__ B, int ldb,
                       float* __restrict__ C, int ldc,
                       int M, int N, int K,
                       const float* __restrict__ bias,
                       const float* __restrict__ base, int base_ld,
                       int act, int sanitize, int chk) {
    if (chk && g_done) return;
    __shared__ float As[8][128];
    __shared__ float Bs[8][128];
    int tid = threadIdx.x;
    int row0 = blockIdx.y * 128, col0 = blockIdx.x * 128;
    int ty = tid >> 4, tx = tid & 15;
    int ar = tid >> 1;         // 0..127
    int ac = (tid & 1) * 4;    // 0 or 4
    int br = tid >> 5;         // 0..7
    int bc = (tid & 31) * 4;   // 0..124
    float acc[8][8];
#pragma unroll
    for (int i = 0; i < 8; i++)
#pragma unroll
        for (int j = 0; j < 8; j++) acc[i][j] = 0.f;

    for (int k0 = 0; k0 < K; k0 += 8) {
        int gr = row0 + ar;
#pragma unroll
        for (int u = 0; u < 4; u++) {
            int gk = k0 + ac + u;
            float v = 0.f;
            if (gr < M && gk < K) v = A[(size_t)gr * lda + gk];
            if (sanitize) v = sanitize_f(v);
            As[ac + u][ar] = v;
        }
        int gk = k0 + br;
#pragma unroll
        for (int u = 0; u < 4; u++) {
            int gc = col0 + bc + u;
            Bs[br][bc + u] = (gk < K && gc < N) ? B[(size_t)gk * ldb + gc] : 0.f;
        }
        __syncthreads();
#pragma unroll
        for (int kk = 0; kk < 8; kk++) {
            float a_[8], b_[8];
#pragma unroll
            for (int i = 0; i < 8; i++) a_[i] = As[kk][ty * 8 + i];
#pragma unroll
            for (int j = 0; j < 8; j++) b_[j] = Bs[kk][tx * 8 + j];
#pragma unroll
            for (int i = 0; i < 8; i++)
#pragma unroll
                for (int j = 0; j < 8; j++)
                    acc[i][j] = fmaf(a_[i], b_[j], acc[i][j]);
        }
        __syncthreads();
    }
#pragma unroll
    for (int i = 0; i < 8; i++) {
        int r = row0 + ty * 8 + i;
        if (r >= M) continue;
#pragma unroll
        for (int j = 0; j < 8; j++) {
            int c = col0 + tx * 8 + j;
            if (c >= N) continue;
            float v = acc[i][j];
            if (bias) v += bias[c];
            if (base) v += base[(r >> 9) * base_ld + c];
            if (act == 1) v = gelu_f(v);
            else if (act == 2) v = tanhf(v);
            C[(size_t)r * ldc + c] = v;
        }
    }
}

// ---------------- per-batch constant part of GEMM1 (src/tgt columns + bias) ----------------
__global__ void k_base(const float* __restrict__ src, const float* __restrict__ tgt,
                       const float* __restrict__ w1, const float* __restrict__ b1,
                       float* __restrict__ out) {
    int b = blockIdx.y;
    int j = blockIdx.x * blockDim.x + threadIdx.x;
    if (j >= F4) return;
    float s = b1[j];
    const float* ps = src + b * 513;
    const float* pt = tgt + b * 513;
    for (int i = 0; i < SPATIAL; i++)
        s = fmaf(ps[i], w1[(size_t)(F4 + i) * F4 + j], s);
    for (int i = 0; i < SPATIAL; i++)
        s = fmaf(pt[i], w1[(size_t)(F4 + SPATIAL + i) * F4 + j], s);
    out[b * F4 + j] = s;
}

// ---------------- LayerNorm + exact GELU (row of 1028, in-place) ----------------
__global__ void k_ln_gelu(float* __restrict__ h, const float* __restrict__ g,
                          const float* __restrict__ be) {
    if (g_done) return;
    int row = blockIdx.x, tid = threadIdx.x;
    const int N = F4;
    float* hr = h + (size_t)row * N;
    float s = 0.f, s2 = 0.f;
    for (int j = tid; j < N; j += 256) { float x = hr[j]; s += x; s2 += x * x; }
    __shared__ float sa[256], sb[256];
    sa[tid] = s; sb[tid] = s2;
    __syncthreads();
    for (int o = 128; o > 0; o >>= 1) {
        if (tid < o) { sa[tid] += sa[tid + o]; sb[tid] += sb[tid + o]; }
        __syncthreads();
    }
    float mean = sa[0] / N;
    float var = sb[0] / N - mean * mean;
    float rs = rsqrtf(var + 1e-5f);
    for (int j = tid; j < N; j += 256) {
        float y = (hr[j] - mean) * rs * g[j] + be[j];
        hr[j] = gelu_f(y);
    }
}

// ---------------- sigmoid head: out[row] = sigmoid(hid[row,:]·w + b) (+addc, nan->0) --------
__global__ void k_head(const float* __restrict__ hid, int K, const float* __restrict__ w,
                       const float* __restrict__ b, float* __restrict__ out,
                       float addc, int nanz) {
    if (g_done) return;
    int row = blockIdx.x, tid = threadIdx.x;
    float s = 0.f;
    for (int k = tid; k < K; k += 256) s = fmaf(hid[(size_t)row * K + k], w[k], s);
    __shared__ float sh[256];
    sh[tid] = s;
    __syncthreads();
    for (int o = 128; o > 0; o >>= 1) {
        if (tid < o) sh[tid] += sh[tid + o];
        __syncthreads();
    }
    if (tid == 0) {
        float v = 1.f / (1.f + expf(-(sh[0] + b[0])));
        if (nanz && isnan(v)) v = 0.f;
        out[row] = v + addc;
    }
}

// ---------------- update: new = damping*old + gamma*alpha*scale*f; per-row partials --------
__global__ void k_update(const float* __restrict__ fd, const float* __restrict__ cs_p,
                         const float* __restrict__ ts_p) {
    if (g_done) return;
    int row = blockIdx.x, tid = threadIdx.x;
    float gam = g_gamma[row];
    float ac = gam * g_alpha_c[row] * (*cs_p);
    float at = gam * g_alpha_t[row] * (*ts_p);
    float dc2 = 0.f, dt2 = 0.f, sc2 = 0.f, st2 = 0.f;
    for (int j = tid; j < F2; j += 256) {
        float fdv = fd[j < NF ? j : j - NF];
        float c = g_ct[(size_t)row * F4 + j];
        float nc = fmaf(fdv, c, ac * g_fc[(size_t)row * F2 + j]);
        g_new[(size_t)row * F4 + j] = nc;
        float d = nc - c; dc2 += d * d; sc2 += nc * nc;
        float t = g_ct[(size_t)row * F4 + F2 + j];
        float nt = fmaf(fdv, t, at * g_ft[(size_t)row * F2 + j]);
        g_new[(size_t)row * F4 + F2 + j] = nt;
        d = nt - t; dt2 += d * d; st2 += nt * nt;
    }
    __shared__ float s0[256], s1[256], s2[256], s3[256];
    s0[tid] = dc2; s1[tid] = dt2; s2[tid] = sc2; s3[tid] = st2;
    __syncthreads();
    for (int o = 128; o > 0; o >>= 1) {
        if (tid < o) { s0[tid] += s0[tid + o]; s1[tid] += s1[tid + o];
                       s2[tid] += s2[tid + o]; s3[tid] += s3[tid + o]; }
        __syncthreads();
    }
    if (tid == 0) {
        g_rn_c[row] = sqrtf(s0[0]);
        g_rn_t[row] = sqrtf(s1[0]);
        g_sq_c[row] = s2[0];
        g_sq_t[row] = s3[0];
    }
}

// ---------------- deterministic global reduce + convergence/clamp decision ----------------
__global__ void k_reduce_finalize() {
    __shared__ float4 sh[1024];
    int tid = threadIdx.x;
    float4 a = make_float4(0.f, 0.f, 0.f, 0.f);
    for (int i = tid; i < ROWS; i += 1024) {
        a.x += g_rn_c[i]; a.y += g_rn_t[i]; a.z += g_sq_c[i]; a.w += g_sq_t[i];
    }
    sh[tid] = a;
    __syncthreads();
    for (int o = 512; o > 0; o >>= 1) {
        if (tid < o) {
            sh[tid].x += sh[tid + o].x; sh[tid].y += sh[tid + o].y;
            sh[tid].z += sh[tid + o].z; sh[tid].w += sh[tid + o].w;
        }
        __syncthreads();
    }
    if (tid == 0) {
        if (g_done) {
            g_scal[2] = 0.f;
        } else {
            float dc = sh[0].x / (float)ROWS;
            float dt = sh[0].y / (float)ROWS;
            float nc = sqrtf(sh[0].z);
            float nt = sqrtf(sh[0].w);
            int conv = (dc < TOLV) && (dt < TOLV);
            g_scal[0] = conv ? 1.f : (nc > 10.f ? 10.f / nc : 1.f);
            g_scal[1] = conv ? 1.f : (nt > 10.f ? 10.f / nt : 1.f);
            g_scal[2] = 1.f;
            if (conv) g_done = 1;
        }
    }
}

// ---------------- apply (commit) step ----------------
__global__ void k_apply() {
    if (g_scal[2] == 0.f) return;
    int idx = blockIdx.x * blockDim.x + threadIdx.x;
    if (idx >= ROWS * F4) return;
    int col = idx % F4;
    float sc = (col < F2) ? g_scal[0] : g_scal[1];
    g_ct[idx] = g_new[idx] * sc;
}

// ---------------- host launch ----------------
extern "C" void kernel_launch(void* const* d_in, const int* in_sizes, int n_in,
                              void* d_out, int out_size) {
    const float* carrier = (const float*)d_in[0];
    const float* traj    = (const float*)d_in[1];
    const float* srcp    = (const float*)d_in[2];
    const float* tgtp    = (const float*)d_in[3];
    const float* cw1 = (const float*)d_in[4];
    const float* cb1 = (const float*)d_in[5];
    const float* cg  = (const float*)d_in[6];
    const float* cbe = (const float*)d_in[7];
    const float* cw2 = (const float*)d_in[8];
    const float* cb2 = (const float*)d_in[9];
    const float* tw1 = (const float*)d_in[10];
    const float* tb1 = (const float*)d_in[11];
    const float* tg  = (const float*)d_in[12];
    const float* tbe = (const float*)d_in[13];
    const float* tw2 = (const float*)d_in[14];
    const float* tb2 = (const float*)d_in[15];
    const float* fd  = (const float*)d_in[16];
    const float* dw1 = (const float*)d_in[17];
    const float* db1 = (const float*)d_in[18];
    const float* dw2 = (const float*)d_in[19];
    const float* db2 = (const float*)d_in[20];
    const float* sw1 = (const float*)d_in[21];
    const float* sb1 = (const float*)d_in[22];
    const float* sw2 = (const float*)d_in[23];
    const float* sb2 = (const float*)d_in[24];
    const float* csc = (const float*)d_in[25];
    const float* tsc = (const float*)d_in[26];
    float* out = (float*)d_out;

    float *p_ct, *p_h, *p_fc, *p_ft, *p_hdc, *p_hdt, *p_hs;
    float *p_ac, *p_at, *p_gm, *p_bc, *p_bt, *p_Br, *p_Bi;
    cudaGetSymbolAddress((void**)&p_ct,  g_ct);
    cudaGetSymbolAddress((void**)&p_h,   g_h);
    cudaGetSymbolAddress((void**)&p_fc,  g_fc);
    cudaGetSymbolAddress((void**)&p_ft,  g_ft);
    cudaGetSymbolAddress((void**)&p_hdc, g_hdc);
    cudaGetSymbolAddress((void**)&p_hdt, g_hdt);
    cudaGetSymbolAddress((void**)&p_hs,  g_hs);
    cudaGetSymbolAddress((void**)&p_ac,  g_alpha_c);
    cudaGetSymbolAddress((void**)&p_at,  g_alpha_t);
    cudaGetSymbolAddress((void**)&p_gm,  g_gamma);
    cudaGetSymbolAddress((void**)&p_bc,  g_base_c);
    cudaGetSymbolAddress((void**)&p_bt,  g_base_t);
    cudaGetSymbolAddress((void**)&p_Br,  g_Br);
    cudaGetSymbolAddress((void**)&p_Bi,  g_Bi);

    dim3 th(256);
    auto gemmGrid = [](int N, int M) { return dim3((N + 127) / 128, (M + 127) / 128); };

    // 0) tables + done reset
    k_init_tables<<<(SPATIAL * NF + 255) / 256, 256>>>();

    // 1) rfft as DFT-GEMM: [4096,512] @ [512,514] -> g_ct (c cols / t cols)
    k_gemm<<<gemmGrid(F2, ROWS), th>>>(carrier, SPATIAL, p_Br, F2, p_ct, F4,
                                       ROWS, F2, SPATIAL, nullptr, nullptr, 0, 0, 0, 0);
    k_gemm<<<gemmGrid(F2, ROWS), th>>>(traj, SPATIAL, p_Br, F2, p_ct + F2, F4,
                                       ROWS, F2, SPATIAL, nullptr, nullptr, 0, 0, 0, 0);

    // 2) per-batch constant base = [src|tgt] @ w1[1028:2052] + b1
    dim3 bg((F4 + 255) / 256, BSZ);
    k_base<<<bg, th>>>(srcp, tgtp, cw1, cb1, p_bc);
    k_base<<<bg, th>>>(srcp, tgtp, tw1, tb1, p_bt);

    // 3) 20 fixed-point steps
    for (int s = 0; s < MAX_STEPS; s++) {
        // carrier freq-net
        k_gemm<<<gemmGrid(F4, ROWS), th>>>(p_ct, F4, cw1, F4, p_h, F4,
                                           ROWS, F4, F4, nullptr, p_bc, F4, 0, 0, 1);
        k_ln_gelu<<<ROWS, th>>>(p_h, cg, cbe);
        k_gemm<<<gemmGrid(F2, ROWS), th>>>(p_h, F4, cw2, F2, p_fc, F2,
                                           ROWS, F2, F4, cb2, nullptr, 0, 2, 0, 1);
        // trajectory freq-net
        k_gemm<<<gemmGrid(F4, ROWS), th>>>(p_ct, F4, tw1, F4, p_h, F4,
                                           ROWS, F4, F4, nullptr, p_bt, F4, 0, 0, 1);
        k_ln_gelu<<<ROWS, th>>>(p_h, tg, tbe);
        k_gemm<<<gemmGrid(F2, ROWS), th>>>(p_h, F4, tw2, F2, p_ft, F2,
                                           ROWS, F2, F4, tb2, nullptr, 0, 2, 0, 1);
        // gating MLP hiddens (sanitized inputs, gelu epilogue)
        k_gemm<<<gemmGrid(NF, ROWS), th>>>(p_ct, F4, dw1, NF, p_hdc, NF,
                                           ROWS, NF, F2, db1, nullptr, 0, 1, 1, 1);
        k_gemm<<<gemmGrid(NF, ROWS), th>>>(p_ct + F2, F4, dw1, NF, p_hdt, NF,
                                           ROWS, NF, F2, db1, nullptr, 0, 1, 1, 1);
        k_gemm<<<gemmGrid(FH, ROWS), th>>>(p_ct, F4, sw1, FH, p_hs, FH,
                                           ROWS, FH, F2, sb1, nullptr, 0, 1, 1, 1);
        // sigmoid heads
        k_head<<<ROWS, th>>>(p_hdc, NF, dw2, db2, p_ac, 0.0f, 1);
        k_head<<<ROWS, th>>>(p_hdt, NF, dw2, db2, p_at, 0.0f, 1);
        k_head<<<ROWS, th>>>(p_hs, FH, sw2, sb2, p_gm, 0.5f, 0);
        // update + convergence/clamp + commit
        k_update<<<ROWS, th>>>(fd, csc, tsc);
        k_reduce_finalize<<<1, 1024>>>();
        k_apply<<<(ROWS * F4 + 255) / 256, th>>>();
    }

    // 4) irfft as DFT-GEMM: [4096,514] @ [514,512] -> outputs
    k_gemm<<<gemmGrid(SPATIAL, ROWS), th>>>(p_ct, F4, p_Bi, SPATIAL, out, SPATIAL,
                                            ROWS, SPATIAL, F2, nullptr, nullptr, 0, 0, 0, 0);
    k_gemm<<<gemmGrid(SPATIAL, ROWS), th>>>(p_ct + F2, F4, p_Bi, SPATIAL,
                                            out + (size_t)ROWS * SPATIAL, SPATIAL,
                                            ROWS, SPATIAL, F2, nullptr, nullptr, 0, 0, 0, 0);
    (void)in_sizes; (void)n_in; (void)out_size;
}

// round 2
// speedup vs baseline: 2.2446x; 2.2446x over previous
#include <cuda_runtime.h>
#include <math.h>
#include <stdint.h>

// ---------------- problem constants ----------------
#define BSZ 8
#define SEQ 512
#define ROWS 4096          // BSZ*SEQ
#define SPATIAL 512
#define NF 257             // rfft bins
#define F2 514
#define F4 1028
#define FH 128             // F//2
#define MAX_STEPS 20
#define TOLV 1e-3f

// ---------------- device scratch (static, no allocation) ----------------
__device__ float g_ct[ROWS * F4];     // row r: [c (514) | t (514)]  => also viewable as [8192 x 514]
__device__ float g_new[ROWS * F4];
__device__ float g_h[ROWS * F4];      // freq-net hidden (reused c then t)
__device__ float g_fc[ROWS * F2];
__device__ float g_ft[ROWS * F2];
__device__ float g_hd[ROWS * 2 * NF]; // merged gating hidden: rows interleaved c,t
__device__ float g_hs[ROWS * FH];
__device__ float g_alpha_ct[ROWS * 2];
__device__ float g_gamma[ROWS];
__device__ float g_base_c[BSZ * F4];
__device__ float g_base_t[BSZ * F4];
__device__ float g_rn_c[ROWS], g_rn_t[ROWS], g_sq_c[ROWS], g_sq_t[ROWS];
__device__ float g_scal[4];           // [0]=scale_c [1]=scale_t [2]=apply_enable
__device__ int   g_done;
__device__ float g_Br[SPATIAL * F2];  // rfft matrix  [n][2k | 2k+1]
__device__ float g_Bi[F2 * SPATIAL];  // irfft matrix [2k|2k+1][n]

// ---------------- device helpers ----------------
__device__ __forceinline__ float gelu_f(float x) {
    return 0.5f * x * (1.0f + erff(x * 0.70710678118654752f));
}
__device__ __forceinline__ float sanitize_f(float v) {
    if (isnan(v)) return 0.0f;
    if (isinf(v)) return v > 0.f ? 1e6f : -1e6f;
    return v;
}
__device__ __forceinline__ float to_tf32(float x) {
    uint32_t u;
    asm("cvt.rna.tf32.f32 %0, %1;" : "=r"(u) : "f"(x));
    return __uint_as_float(u);
}

// ---------------- table init (also resets done flag) ----------------
__global__ void k_init_tables() {
    int idx = blockIdx.x * blockDim.x + threadIdx.x;
    if (idx == 0) g_done = 0;
    int total = SPATIAL * NF;
    if (idx >= total) return;
    int n = idx / NF, k = idx % NF;
    double r = (double)((k * n) & 511) / 256.0;
    double sv, cv;
    sincospi(r, &sv, &cv);
    g_Br[n * F2 + 2 * k]     = (float)cv;
    g_Br[n * F2 + 2 * k + 1] = (float)(-sv);
    double w = (k == 0 || k == NF - 1) ? 1.0 : 2.0;
    g_Bi[(2 * k) * SPATIAL + n]     = (float)(w * cv / 512.0);
    g_Bi[(2 * k + 1) * SPATIAL + n] = (float)(-w * sv / 512.0);
}

// =====================================================================
// TF32 tensor-core GEMM: C = act(A@B + bias[col] + base[batch][col])
// block tile 128x128, BK=32, 8 warps (2M x 4N), warp tile 64x32
// =====================================================================
__global__ void k_gemm_tc(const float* __restrict__ A, int lda,
                          const float* __restrict__ B, int ldb,
                          float* __restrict__ C, int ldc,
                          int M, int N, int K,
                          const float* __restrict__ bias,
                          const float* __restrict__ base, int base_ld,
                          int act, int sanitize, int chk) {
    if (chk && g_done) return;
    __shared__ float As[128][36];   // banks: 4*gid + tg -> conflict free
    __shared__ float Bs[32][136];   // banks: 8*tg + gid -> conflict free

    const int tid = threadIdx.x;
    const int warp = tid >> 5, lane = tid & 31;
    const int gid = lane >> 2, tg = lane & 3;
    const int wm = warp & 1, wn = warp >> 1;      // 2 x 4 warp grid
    const int row0 = blockIdx.y * 128, col0 = blockIdx.x * 128;

    float acc[4][4][4];
#pragma unroll
    for (int mi = 0; mi < 4; mi++)
#pragma unroll
        for (int ni = 0; ni < 4; ni++)
#pragma unroll
            for (int q = 0; q < 4; q++) acc[mi][ni][q] = 0.f;

    // staging registers
    float ra[16], rb[16];
    const int a_k = tid & 31;           // k within tile
    const int a_r0 = tid >> 5;          // row start (stride 8)
    const int b_n = tid & 127;          // n within tile
    const int b_k0 = tid >> 7;          // k start (stride 2)

    const int nkb = (K + 31) / 32;

    // prefetch kblock 0
    {
        int k0 = 0;
#pragma unroll
        for (int i = 0; i < 16; i++) {
            int r = row0 + a_r0 + i * 8;
            int gk = k0 + a_k;
            float v = (r < M && gk < K) ? A[(size_t)r * lda + gk] : 0.f;
            if (sanitize) v = sanitize_f(v);
            ra[i] = v;
        }
#pragma unroll
        for (int i = 0; i < 16; i++) {
            int gk = k0 + b_k0 + i * 2;
            int c = col0 + b_n;
            rb[i] = (gk < K && c < N) ? B[(size_t)gk * ldb + c] : 0.f;
        }
    }

    for (int kb = 0; kb < nkb; kb++) {
        // commit staged tile to smem (convert to tf32 once here)
#pragma unroll
        for (int i = 0; i < 16; i++)
            As[a_r0 + i * 8][a_k] = to_tf32(ra[i]);
#pragma unroll
        for (int i = 0; i < 16; i++)
            Bs[b_k0 + i * 2][b_n] = to_tf32(rb[i]);
        __syncthreads();

        // prefetch next kblock while computing
        if (kb + 1 < nkb) {
            int k0 = (kb + 1) * 32;
#pragma unroll
            for (int i = 0; i < 16; i++) {
                int r = row0 + a_r0 + i * 8;
                int gk = k0 + a_k;
                float v = (r < M && gk < K) ? A[(size_t)r * lda + gk] : 0.f;
                if (sanitize) v = sanitize_f(v);
                ra[i] = v;
            }
#pragma unroll
            for (int i = 0; i < 16; i++) {
                int gk = k0 + b_k0 + i * 2;
                int c = col0 + b_n;
                rb[i] = (gk < K && c < N) ? B[(size_t)gk * ldb + c] : 0.f;
            }
        }

#pragma unroll
        for (int s = 0; s < 4; s++) {
            float af[4][4];
#pragma unroll
            for (int mi = 0; mi < 4; mi++) {
                int r = wm * 64 + mi * 16 + gid;
                af[mi][0] = As[r][s * 8 + tg];
                af[mi][1] = As[r + 8][s * 8 + tg];
                af[mi][2] = As[r][s * 8 + tg + 4];
                af[mi][3] = As[r + 8][s * 8 + tg + 4];
            }
            float bf[4][2];
#pragma unroll
            for (int ni = 0; ni < 4; ni++) {
                int n = wn * 32 + ni * 8 + gid;
                bf[ni][0] = Bs[s * 8 + tg][n];
                bf[ni][1] = Bs[s * 8 + tg + 4][n];
            }
#pragma unroll
            for (int mi = 0; mi < 4; mi++)
#pragma unroll
                for (int ni = 0; ni < 4; ni++) {
                    asm volatile(
                        "mma.sync.aligned.m16n8k8.row.col.f32.tf32.tf32.f32 "
                        "{%0,%1,%2,%3}, {%4,%5,%6,%7}, {%8,%9}, {%0,%1,%2,%3};"
                        : "+f"(acc[mi][ni][0]), "+f"(acc[mi][ni][1]),
                          "+f"(acc[mi][ni][2]), "+f"(acc[mi][ni][3])
                        : "r"(__float_as_uint(af[mi][0])), "r"(__float_as_uint(af[mi][1])),
                          "r"(__float_as_uint(af[mi][2])), "r"(__float_as_uint(af[mi][3])),
                          "r"(__float_as_uint(bf[ni][0])), "r"(__float_as_uint(bf[ni][1])));
                }
        }
        __syncthreads();
    }

    // epilogue
#pragma unroll
    for (int mi = 0; mi < 4; mi++) {
#pragma unroll
        for (int ni = 0; ni < 4; ni++) {
#pragma unroll
            for (int q = 0; q < 4; q++) {
                int r = row0 + wm * 64 + mi * 16 + gid + (q >> 1) * 8;
                int c = col0 + wn * 32 + ni * 8 + tg * 2 + (q & 1);
                if (r >= M || c >= N) continue;
                float v = acc[mi][ni][q];
                if (bias) v += bias[c];
                if (base) v += base[(r >> 9) * base_ld + c];
                if (act == 1) v = gelu_f(v);
                else if (act == 2) v = tanhf(v);
                C[(size_t)r * ldc + c] = v;
            }
        }
    }
}

// ---------------- fp32 SGEMM (kept for FFT transforms, run once) ----------------
__global__ void k_gemm(const float* __restrict__ A, int lda,
                       const float* __restrict__ B, int ldb,
                       float* __restrict__ C, int ldc,
                       int M, int N, int K) {
    __shared__ float As[8][128];
    __shared__ float Bs[8][128];
    int tid = threadIdx.x;
    int row0 = blockIdx.y * 128, col0 = blockIdx.x * 128;
    int ty = tid >> 4, tx = tid & 15;
    int ar = tid >> 1;
    int ac = (tid & 1) * 4;
    int br = tid >> 5;
    int bc = (tid & 31) * 4;
    float acc[8][8];
#pragma unroll
    for (int i = 0; i < 8; i++)
#pragma unroll
        for (int j = 0; j < 8; j++) acc[i][j] = 0.f;

    for (int k0 = 0; k0 < K; k0 += 8) {
        int gr = row0 + ar;
#pragma unroll
        for (int u = 0; u < 4; u++) {
            int gk = k0 + ac + u;
            As[ac + u][ar] = (gr < M && gk < K) ? A[(size_t)gr * lda + gk] : 0.f;
        }
        int gk = k0 + br;
#pragma unroll
        for (int u = 0; u < 4; u++) {
            int gc = col0 + bc + u;
            Bs[br][bc + u] = (gk < K && gc < N) ? B[(size_t)gk * ldb + gc] : 0.f;
        }
        __syncthreads();
#pragma unroll
        for (int kk = 0; kk < 8; kk++) {
            float a_[8], b_[8];
#pragma unroll
            for (int i = 0; i < 8; i++) a_[i] = As[kk][ty * 8 + i];
#pragma unroll
            for (int j = 0; j < 8; j++) b_[j] = Bs[kk][tx * 8 + j];
#pragma unroll
            for (int i = 0; i < 8; i++)
#pragma unroll
                for (int j = 0; j < 8; j++)
                    acc[i][j] = fmaf(a_[i], b_[j], acc[i][j]);
        }
        __syncthreads();
    }
#pragma unroll
    for (int i = 0; i < 8; i++) {
        int r = row0 + ty * 8 + i;
        if (r >= M) continue;
#pragma unroll
        for (int j = 0; j < 8; j++) {
            int c = col0 + tx * 8 + j;
            if (c < N) C[(size_t)r * ldc + c] = acc[i][j];
        }
    }
}

// ---------------- per-batch constant part of GEMM1 (coalesced, k-split) ----------------
__global__ void k_base(const float* __restrict__ src, const float* __restrict__ tgt,
                       const float* __restrict__ w1, const float* __restrict__ b1,
                       float* __restrict__ out) {
    int b = blockIdx.y;
    int tid = threadIdx.x;
    int jj = tid & 31;
    int ks = tid >> 5;                 // 0..7
    int j = blockIdx.x * 32 + jj;
    float s = 0.f;
    if (j < F4) {
        const float* ps = src + b * 513;
        const float* pt = tgt + b * 513;
        for (int k = ks * 128; k < ks * 128 + 128; k++) {
            float x = (k < 512) ? ps[k] : pt[k - 512];
            s = fmaf(x, w1[(size_t)(F4 + k) * F4 + j], s);
        }
    }
    __shared__ float sh[8][32];
    sh[ks][jj] = s;
    __syncthreads();
    if (ks == 0 && j < F4) {
        float t = b1[j];
#pragma unroll
        for (int q = 0; q < 8; q++) t += sh[q][jj];
        out[b * F4 + j] = t;
    }
}

// ---------------- LayerNorm + exact GELU (row of 1028, in-place) ----------------
__global__ void k_ln_gelu(float* __restrict__ h, const float* __restrict__ g,
                          const float* __restrict__ be) {
    if (g_done) return;
    int row = blockIdx.x, tid = threadIdx.x;
    const int N = F4;
    float* hr = h + (size_t)row * N;
    float s = 0.f, s2 = 0.f;
    for (int j = tid; j < N; j += 256) { float x = hr[j]; s += x; s2 += x * x; }
    __shared__ float sa[256], sb[256];
    sa[tid] = s; sb[tid] = s2;
    __syncthreads();
    for (int o = 128; o > 0; o >>= 1) {
        if (tid < o) { sa[tid] += sa[tid + o]; sb[tid] += sb[tid + o]; }
        __syncthreads();
    }
    float mean = sa[0] / N;
    float var = sb[0] / N - mean * mean;
    float rs = rsqrtf(var + 1e-5f);
    for (int j = tid; j < N; j += 256) {
        float y = (hr[j] - mean) * rs * g[j] + be[j];
        hr[j] = gelu_f(y);
    }
}

// ---------------- sigmoid head ----------------
__global__ void k_head(const float* __restrict__ hid, int K, const float* __restrict__ w,
                       const float* __restrict__ b, float* __restrict__ out,
                       float addc, int nanz) {
    if (g_done) return;
    int row = blockIdx.x, tid = threadIdx.x;
    float s = 0.f;
    for (int k = tid; k < K; k += 256) s = fmaf(hid[(size_t)row * K + k], w[k], s);
    __shared__ float sh[256];
    sh[tid] = s;
    __syncthreads();
    for (int o = 128; o > 0; o >>= 1) {
        if (tid < o) sh[tid] += sh[tid + o];
        __syncthreads();
    }
    if (tid == 0) {
        float v = 1.f / (1.f + expf(-(sh[0] + b[0])));
        if (nanz && isnan(v)) v = 0.f;
        out[row] = v + addc;
    }
}

// ---------------- update: new = damping*old + gamma*alpha*scale*f; per-row partials ----
__global__ void k_update(const float* __restrict__ fd, const float* __restrict__ cs_p,
                         const float* __restrict__ ts_p) {
    if (g_done) return;
    int row = blockIdx.x, tid = threadIdx.x;
    float gam = g_gamma[row];
    float ac = gam * g_alpha_ct[2 * row] * (*cs_p);
    float at = gam * g_alpha_ct[2 * row + 1] * (*ts_p);
    float dc2 = 0.f, dt2 = 0.f, sc2 = 0.f, st2 = 0.f;
    for (int j = tid; j < F2; j += 256) {
        float fdv = fd[j < NF ? j : j - NF];
        float c = g_ct[(size_t)row * F4 + j];
        float nc = fmaf(fdv, c, ac * g_fc[(size_t)row * F2 + j]);
        g_new[(size_t)row * F4 + j] = nc;
        float d = nc - c; dc2 += d * d; sc2 += nc * nc;
        float t = g_ct[(size_t)row * F4 + F2 + j];
        float nt = fmaf(fdv, t, at * g_ft[(size_t)row * F2 + j]);
        g_new[(size_t)row * F4 + F2 + j] = nt;
        d = nt - t; dt2 += d * d; st2 += nt * nt;
    }
    __shared__ float s0[256], s1[256], s2[256], s3[256];
    s0[tid] = dc2; s1[tid] = dt2; s2[tid] = sc2; s3[tid] = st2;
    __syncthreads();
    for (int o = 128; o > 0; o >>= 1) {
        if (tid < o) { s0[tid] += s0[tid + o]; s1[tid] += s1[tid + o];
                       s2[tid] += s2[tid + o]; s3[tid] += s3[tid + o]; }
        __syncthreads();
    }
    if (tid == 0) {
        g_rn_c[row] = sqrtf(s0[0]);
        g_rn_t[row] = sqrtf(s1[0]);
        g_sq_c[row] = s2[0];
        g_sq_t[row] = s3[0];
    }
}

// ---------------- deterministic global reduce + convergence/clamp decision ----------------
__global__ void k_reduce_finalize() {
    __shared__ float4 sh[1024];
    int tid = threadIdx.x;
    float4 a = make_float4(0.f, 0.f, 0.f, 0.f);
    for (int i = tid; i < ROWS; i += 1024) {
        a.x += g_rn_c[i]; a.y += g_rn_t[i]; a.z += g_sq_c[i]; a.w += g_sq_t[i];
    }
    sh[tid] = a;
    __syncthreads();
    for (int o = 512; o > 0; o >>= 1) {
        if (tid < o) {
            sh[tid].x += sh[tid + o].x; sh[tid].y += sh[tid + o].y;
            sh[tid].z += sh[tid + o].z; sh[tid].w += sh[tid + o].w;
        }
        __syncthreads();
    }
    if (tid == 0) {
        if (g_done) {
            g_scal[2] = 0.f;
        } else {
            float dc = sh[0].x / (float)ROWS;
            float dt = sh[0].y / (float)ROWS;
            float nc = sqrtf(sh[0].z);
            float nt = sqrtf(sh[0].w);
            int conv = (dc < TOLV) && (dt < TOLV);
            g_scal[0] = conv ? 1.f : (nc > 10.f ? 10.f / nc : 1.f);
            g_scal[1] = conv ? 1.f : (nt > 10.f ? 10.f / nt : 1.f);
            g_scal[2] = 1.f;
            if (conv) g_done = 1;
        }
    }
}

// ---------------- apply (commit) step ----------------
__global__ void k_apply() {
    if (g_scal[2] == 0.f) return;
    int idx = blockIdx.x * blockDim.x + threadIdx.x;
    if (idx >= ROWS * F4) return;
    int col = idx % F4;
    float sc = (col < F2) ? g_scal[0] : g_scal[1];
    g_ct[idx] = g_new[idx] * sc;
}

// ---------------- host launch ----------------
extern "C" void kernel_launch(void* const* d_in, const int* in_sizes, int n_in,
                              void* d_out, int out_size) {
    const float* carrier = (const float*)d_in[0];
    const float* traj    = (const float*)d_in[1];
    const float* srcp    = (const float*)d_in[2];
    const float* tgtp    = (const float*)d_in[3];
    const float* cw1 = (const float*)d_in[4];
    const float* cb1 = (const float*)d_in[5];
    const float* cg  = (const float*)d_in[6];
    const float* cbe = (const float*)d_in[7];
    const float* cw2 = (const float*)d_in[8];
    const float* cb2 = (const float*)d_in[9];
    const float* tw1 = (const float*)d_in[10];
    const float* tb1 = (const float*)d_in[11];
    const float* tg_  = (const float*)d_in[12];
    const float* tbe = (const float*)d_in[13];
    const float* tw2 = (const float*)d_in[14];
    const float* tb2 = (const float*)d_in[15];
    const float* fd  = (const float*)d_in[16];
    const float* dw1 = (const float*)d_in[17];
    const float* db1 = (const float*)d_in[18];
    const float* dw2 = (const float*)d_in[19];
    const float* db2 = (const float*)d_in[20];
    const float* sw1 = (const float*)d_in[21];
    const float* sb1 = (const float*)d_in[22];
    const float* sw2 = (const float*)d_in[23];
    const float* sb2 = (const float*)d_in[24];
    const float* csc = (const float*)d_in[25];
    const float* tsc = (const float*)d_in[26];
    float* out = (float*)d_out;

    float *p_ct, *p_h, *p_fc, *p_ft, *p_hd, *p_hs;
    float *p_act, *p_gm, *p_bc, *p_bt, *p_Br, *p_Bi;
    cudaGetSymbolAddress((void**)&p_ct,  g_ct);
    cudaGetSymbolAddress((void**)&p_h,   g_h);
    cudaGetSymbolAddress((void**)&p_fc,  g_fc);
    cudaGetSymbolAddress((void**)&p_ft,  g_ft);
    cudaGetSymbolAddress((void**)&p_hd,  g_hd);
    cudaGetSymbolAddress((void**)&p_hs,  g_hs);
    cudaGetSymbolAddress((void**)&p_act, g_alpha_ct);
    cudaGetSymbolAddress((void**)&p_gm,  g_gamma);
    cudaGetSymbolAddress((void**)&p_bc,  g_base_c);
    cudaGetSymbolAddress((void**)&p_bt,  g_base_t);
    cudaGetSymbolAddress((void**)&p_Br,  g_Br);
    cudaGetSymbolAddress((void**)&p_Bi,  g_Bi);

    dim3 th(256);
    auto grid = [](int N, int M) { return dim3((N + 127) / 128, (M + 127) / 128); };

    // 0) tables + done reset
    k_init_tables<<<(SPATIAL * NF + 255) / 256, 256>>>();

    // 1) rfft as DFT-GEMM (fp32 for accuracy; runs once)
    k_gemm<<<grid(F2, ROWS), th>>>(carrier, SPATIAL, p_Br, F2, p_ct, F4, ROWS, F2, SPATIAL);
    k_gemm<<<grid(F2, ROWS), th>>>(traj, SPATIAL, p_Br, F2, p_ct + F2, F4, ROWS, F2, SPATIAL);

    // 2) per-batch constant base = [src|tgt] @ w1[1028:2052] + b1
    dim3 bg((F4 + 31) / 32, BSZ);
    k_base<<<bg, th>>>(srcp, tgtp, cw1, cb1, p_bc);
    k_base<<<bg, th>>>(srcp, tgtp, tw1, tb1, p_bt);

    // 3) 20 fixed-point steps (TF32 tensor-core GEMMs)
    for (int s = 0; s < MAX_STEPS; s++) {
        // carrier freq-net
        k_gemm_tc<<<grid(F4, ROWS), th>>>(p_ct, F4, cw1, F4, p_h, F4,
                                          ROWS, F4, F4, nullptr, p_bc, F4, 0, 0, 1);
        k_ln_gelu<<<ROWS, th>>>(p_h, cg, cbe);
        k_gemm_tc<<<grid(F2, ROWS), th>>>(p_h, F4, cw2, F2, p_fc, F2,
                                          ROWS, F2, F4, cb2, nullptr, 0, 2, 0, 1);
        // trajectory freq-net
        k_gemm_tc<<<grid(F4, ROWS), th>>>(p_ct, F4, tw1, F4, p_h, F4,
                                          ROWS, F4, F4, nullptr, p_bt, F4, 0, 0, 1);
        k_ln_gelu<<<ROWS, th>>>(p_h, tg_, tbe);
        k_gemm_tc<<<grid(F2, ROWS), th>>>(p_h, F4, tw2, F2, p_ft, F2,
                                          ROWS, F2, F4, tb2, nullptr, 0, 2, 0, 1);
        // merged gating hidden: g_ct viewed as [8192 x 514]
        k_gemm_tc<<<grid(NF, 2 * ROWS), th>>>(p_ct, F2, dw1, NF, p_hd, NF,
                                              2 * ROWS, NF, F2, db1, nullptr, 0, 1, 1, 1);
        k_gemm_tc<<<grid(FH, ROWS), th>>>(p_ct, F4, sw1, FH, p_hs, FH,
                                          ROWS, FH, F2, sb1, nullptr, 0, 1, 1, 1);
        // sigmoid heads
        k_head<<<2 * ROWS, th>>>(p_hd, NF, dw2, db2, p_act, 0.0f, 1);
        k_head<<<ROWS, th>>>(p_hs, FH, sw2, sb2, p_gm, 0.5f, 0);
        // update + convergence/clamp + commit
        k_update<<<ROWS, th>>>(fd, csc, tsc);
        k_reduce_finalize<<<1, 1024>>>();
        k_apply<<<(ROWS * F4 + 255) / 256, th>>>();
    }

    // 4) irfft as DFT-GEMM (fp32)
    k_gemm<<<grid(SPATIAL, ROWS), th>>>(p_ct, F4, p_Bi, SPATIAL, out, SPATIAL,
                                        ROWS, SPATIAL, F2);
    k_gemm<<<grid(SPATIAL, ROWS), th>>>(p_ct + F2, F4, p_Bi, SPATIAL,
                                        out + (size_t)ROWS * SPATIAL, SPATIAL,
                                        ROWS, SPATIAL, F2);
    (void)in_sizes; (void)n_in; (void)out_size;
}

// round 4
// speedup vs baseline: 3.5381x; 1.5763x over previous
#include <cuda_runtime.h>
#include <cuda_fp16.h>
#include <math.h>
#include <stdint.h>

// ---------------- problem constants ----------------
#define BSZ 8
#define SEQ 512
#define ROWS 4096          // BSZ*SEQ
#define SPATIAL 512
#define NF 257             // rfft bins
#define F2 514
#define F4 1028
#define FH 128             // F//2
#define MAX_STEPS 20
#define TOLV 1e-3f
#define KP_F4 1056         // 1028 -> 33*32
#define KP_F2 544          // 514  -> 17*32

// ---------------- device scratch (static, no allocation) ----------------
__device__ float g_ct[ROWS * F4];     // row r: [c (514) | t (514)]; also [8192 x 514]
__device__ float g_new[ROWS * F4];
__device__ float g_h[ROWS * F4];
__device__ float g_fc[ROWS * F2];
__device__ float g_ft[ROWS * F2];
__device__ float g_hd[ROWS * 2 * NF];
__device__ float g_hs[ROWS * FH];
__device__ float g_alpha_ct[ROWS * 2];
__device__ float g_gamma[ROWS];
__device__ float g_base_c[BSZ * F4];
__device__ float g_base_t[BSZ * F4];
__device__ float g_rn_c[ROWS], g_rn_t[ROWS], g_sq_c[ROWS], g_sq_t[ROWS];
__device__ float g_scal[4];
__device__ int   g_done;
__device__ float g_Br[SPATIAL * F2];  // fp32 rfft matrix
__device__ float g_Bi[F2 * SPATIAL];  // fp32 irfft matrix
// transposed K-major fp16 weights (zero-padded K)
__device__ __half g_cw1T[F4 * KP_F4];
__device__ __half g_tw1T[F4 * KP_F4];
__device__ __half g_cw2T[F2 * KP_F4];
__device__ __half g_tw2T[F2 * KP_F4];
__device__ __half g_dw1T[NF * KP_F2];
__device__ __half g_sw1T[FH * KP_F2];

// ---------------- device helpers ----------------
__device__ __forceinline__ float gelu_f(float x) {
    return 0.5f * x * (1.0f + erff(x * 0.70710678118654752f));
}
__device__ __forceinline__ float sanitize_f(float v) {
    if (isnan(v)) return 0.0f;
    if (isinf(v)) return v > 0.f ? 1e6f : -1e6f;
    return v;
}

// ---------------- table init ----------------
__global__ void k_init_tables() {
    int idx = blockIdx.x * blockDim.x + threadIdx.x;
    if (idx == 0) g_done = 0;
    int total = SPATIAL * NF;
    if (idx >= total) return;
    int n = idx / NF, k = idx % NF;
    double r = (double)((k * n) & 511) / 256.0;
    double sv, cv;
    sincospi(r, &sv, &cv);
    g_Br[n * F2 + 2 * k]     = (float)cv;
    g_Br[n * F2 + 2 * k + 1] = (float)(-sv);
    double w = (k == 0 || k == NF - 1) ? 1.0 : 2.0;
    g_Bi[(2 * k) * SPATIAL + n]     = (float)(w * cv / 512.0);
    g_Bi[(2 * k + 1) * SPATIAL + n] = (float)(-w * sv / 512.0);
}

// ---------------- weight transpose: W[K][N] -> WT[N][Kpad] fp16 ----------------
__global__ void k_transpose_h(const float* __restrict__ W, int K, int N,
                              __half* __restrict__ WT, int Kpad) {
    int k = blockIdx.x * 256 + threadIdx.x;
    int n = blockIdx.y;
    if (k >= Kpad) return;
    float v = (k < K) ? W[(size_t)k * N + n] : 0.f;
    WT[(size_t)n * Kpad + k] = __float2half_rn(v);
}

// =====================================================================
// FP16 tensor-core GEMM: C = act(A@BT^T + bias + base)
// block tile 128x128, BK=32, 8 warps (2M x 4N), warp tile 64x32
// A fp32 row-major [M][lda]; BT fp16 K-major [N][ldbt] (ldbt % 32 == 0)
// double-buffered smem, one sync per kblock
// =====================================================================
__global__ __launch_bounds__(256) void k_gemm_h(
    const float* __restrict__ A, int lda,
    const __half* __restrict__ BT, int ldbt,
    float* __restrict__ C, int ldc,
    int M, int N, int K,
    const float* __restrict__ bias,
    const float* __restrict__ base, int base_ld,
    int act, int sanitize, int chk) {
    if (chk && g_done) return;

    __shared__ __half As[2][128][40];   // pad 40: word = 20*gid + tg -> conflict-free
    __shared__ __half Bs[2][128][40];

    const int tid = threadIdx.x;
    const int warp = tid >> 5, lane = tid & 31;
    const int gid = lane >> 2, tg = lane & 3;
    const int wm = warp & 1, wn = warp >> 1;      // 2 x 4 warps, warp tile 64x32
    const int row0 = blockIdx.y * 128, col0 = blockIdx.x * 128;

    float acc[4][4][4];
#pragma unroll
    for (int mi = 0; mi < 4; mi++)
#pragma unroll
        for (int ni = 0; ni < 4; ni++)
#pragma unroll
            for (int q = 0; q < 4; q++) acc[mi][ni][q] = 0.f;

    const int nkb = ldbt >> 5;       // K-blocks (BT zero-padded)
    const int str = tid >> 1;        // 0..127  (row for A, n for B)
    const int skh = (tid & 1) * 16;  // k half offset

    float2 a_st[8];
    uint4  b_st[2];

    auto prefetch = [&](int kb) {
        int k0 = kb * 32 + skh;
        int gr = row0 + str;
#pragma unroll
        for (int u = 0; u < 8; u++) {
            int gk = k0 + 2 * u;
            float2 v = make_float2(0.f, 0.f);
            if (gr < M && gk < K)
                v = *(const float2*)(A + (size_t)gr * lda + gk);
            if (sanitize) { v.x = sanitize_f(v.x); v.y = sanitize_f(v.y); }
            a_st[u] = v;
        }
        int nn = col0 + str;
        if (nn < N) {
            const __half* bp = BT + (size_t)nn * ldbt + k0;
            b_st[0] = *(const uint4*)bp;
            b_st[1] = *(const uint4*)(bp + 8);
        } else {
            b_st[0] = make_uint4(0, 0, 0, 0);
            b_st[1] = make_uint4(0, 0, 0, 0);
        }
    };
    auto commit = [&](int buf) {
#pragma unroll
        for (int u = 0; u < 8; u++) {
            __half2 h = __float22half2_rn(a_st[u]);
            *(uint32_t*)&As[buf][str][skh + 2 * u] = *(uint32_t*)&h;
        }
        *(uint4*)&Bs[buf][str][skh] = b_st[0];
        *(uint4*)&Bs[buf][str][skh + 8] = b_st[1];
    };

    prefetch(0);
    commit(0);
    __syncthreads();

    for (int kb = 0; kb < nkb; kb++) {
        int buf = kb & 1;
        if (kb + 1 < nkb) prefetch(kb + 1);
#pragma unroll
        for (int s = 0; s < 2; s++) {
            uint32_t af[4][4], bf[4][2];
#pragma unroll
            for (int mi = 0; mi < 4; mi++) {
                int m = wm * 64 + mi * 16 + gid;
                af[mi][0] = *(const uint32_t*)&As[buf][m][s * 16 + 2 * tg];
                af[mi][1] = *(const uint32_t*)&As[buf][m + 8][s * 16 + 2 * tg];
                af[mi][2] = *(const uint32_t*)&As[buf][m][s * 16 + 2 * tg + 8];
                af[mi][3] = *(const uint32_t*)&As[buf][m + 8][s * 16 + 2 * tg + 8];
            }
#pragma unroll
            for (int ni = 0; ni < 4; ni++) {
                int n = wn * 32 + ni * 8 + gid;
                bf[ni][0] = *(const uint32_t*)&Bs[buf][n][s * 16 + 2 * tg];
                bf[ni][1] = *(const uint32_t*)&Bs[buf][n][s * 16 + 2 * tg + 8];
            }
#pragma unroll
            for (int mi = 0; mi < 4; mi++)
#pragma unroll
                for (int ni = 0; ni < 4; ni++) {
                    asm volatile(
                        "mma.sync.aligned.m16n8k16.row.col.f32.f16.f16.f32 "
                        "{%0,%1,%2,%3}, {%4,%5,%6,%7}, {%8,%9}, {%0,%1,%2,%3};"
                        : "+f"(acc[mi][ni][0]), "+f"(acc[mi][ni][1]),
                          "+f"(acc[mi][ni][2]), "+f"(acc[mi][ni][3])
                        : "r"(af[mi][0]), "r"(af[mi][1]), "r"(af[mi][2]), "r"(af[mi][3]),
                          "r"(bf[ni][0]), "r"(bf[ni][1]));
                }
        }
        if (kb + 1 < nkb) {
            commit(buf ^ 1);
            __syncthreads();
        }
    }

    // epilogue
#pragma unroll
    for (int mi = 0; mi < 4; mi++) {
#pragma unroll
        for (int ni = 0; ni < 4; ni++) {
#pragma unroll
            for (int q = 0; q < 4; q++) {
                int r = row0 + wm * 64 + mi * 16 + gid + (q >> 1) * 8;
                int c = col0 + wn * 32 + ni * 8 + tg * 2 + (q & 1);
                if (r >= M || c >= N) continue;
                float v = acc[mi][ni][q];
                if (bias) v += bias[c];
                if (base) v += base[(r >> 9) * base_ld + c];
                if (act == 1) v = gelu_f(v);
                else if (act == 2) v = tanhf(v);
                C[(size_t)r * ldc + c] = v;
            }
        }
    }
}

// ---------------- fp32 SGEMM (FFT transforms only) ----------------
__global__ void k_gemm(const float* __restrict__ A, int lda,
                       const float* __restrict__ B, int ldb,
                       float* __restrict__ C, int ldc,
                       int M, int N, int K) {
    __shared__ float As[8][128];
    __shared__ float Bs[8][128];
    int tid = threadIdx.x;
    int row0 = blockIdx.y * 128, col0 = blockIdx.x * 128;
    int ty = tid >> 4, tx = tid & 15;
    int ar = tid >> 1, ac = (tid & 1) * 4;
    int br = tid >> 5, bc = (tid & 31) * 4;
    float acc[8][8];
#pragma unroll
    for (int i = 0; i < 8; i++)
#pragma unroll
        for (int j = 0; j < 8; j++) acc[i][j] = 0.f;
    for (int k0 = 0; k0 < K; k0 += 8) {
        int gr = row0 + ar;
#pragma unroll
        for (int u = 0; u < 4; u++) {
            int gk = k0 + ac + u;
            As[ac + u][ar] = (gr < M && gk < K) ? A[(size_t)gr * lda + gk] : 0.f;
        }
        int gk = k0 + br;
#pragma unroll
        for (int u = 0; u < 4; u++) {
            int gc = col0 + bc + u;
            Bs[br][bc + u] = (gk < K && gc < N) ? B[(size_t)gk * ldb + gc] : 0.f;
        }
        __syncthreads();
#pragma unroll
        for (int kk = 0; kk < 8; kk++) {
            float a_[8], b_[8];
#pragma unroll
            for (int i = 0; i < 8; i++) a_[i] = As[kk][ty * 8 + i];
#pragma unroll
            for (int j = 0; j < 8; j++) b_[j] = Bs[kk][tx * 8 + j];
#pragma unroll
            for (int i = 0; i < 8; i++)
#pragma unroll
                for (int j = 0; j < 8; j++)
                    acc[i][j] = fmaf(a_[i], b_[j], acc[i][j]);
        }
        __syncthreads();
    }
#pragma unroll
    for (int i = 0; i < 8; i++) {
        int r = row0 + ty * 8 + i;
        if (r >= M) continue;
#pragma unroll
        for (int j = 0; j < 8; j++) {
            int c = col0 + tx * 8 + j;
            if (c < N) C[(size_t)r * ldc + c] = acc[i][j];
        }
    }
}

// ---------------- per-batch constant base ----------------
__global__ void k_base(const float* __restrict__ src, const float* __restrict__ tgt,
                       const float* __restrict__ w1, const float* __restrict__ b1,
                       float* __restrict__ out) {
    int b = blockIdx.y;
    int tid = threadIdx.x;
    int jj = tid & 31;
    int ks = tid >> 5;
    int j = blockIdx.x * 32 + jj;
    float s = 0.f;
    if (j < F4) {
        const float* ps = src + b * 513;
        const float* pt = tgt + b * 513;
        for (int k = ks * 128; k < ks * 128 + 128; k++) {
            float x = (k < 512) ? ps[k] : pt[k - 512];
            s = fmaf(x, w1[(size_t)(F4 + k) * F4 + j], s);
        }
    }
    __shared__ float sh[8][32];
    sh[ks][jj] = s;
    __syncthreads();
    if (ks == 0 && j < F4) {
        float t = b1[j];
#pragma unroll
        for (int q = 0; q < 8; q++) t += sh[q][jj];
        out[b * F4 + j] = t;
    }
}

// ---------------- LayerNorm + exact GELU (row of 1028, float4) ----------------
__global__ void k_ln_gelu(float* __restrict__ h, const float* __restrict__ g,
                          const float* __restrict__ be) {
    if (g_done) return;
    int row = blockIdx.x, tid = threadIdx.x;
    float4* hr = (float4*)(h + (size_t)row * F4);   // 257 float4
    float s = 0.f, s2 = 0.f;
    for (int j = tid; j < 257; j += 256) {
        float4 x = hr[j];
        s += x.x + x.y + x.z + x.w;
        s2 += x.x * x.x + x.y * x.y + x.z * x.z + x.w * x.w;
    }
    __shared__ float sa[256], sb[256];
    sa[tid] = s; sb[tid] = s2;
    __syncthreads();
    for (int o = 128; o > 0; o >>= 1) {
        if (tid < o) { sa[tid] += sa[tid + o]; sb[tid] += sb[tid + o]; }
        __syncthreads();
    }
    float mean = sa[0] / F4;
    float var = sb[0] / F4 - mean * mean;
    float rs = rsqrtf(var + 1e-5f);
    const float4* g4 = (const float4*)g;
    const float4* b4 = (const float4*)be;
    for (int j = tid; j < 257; j += 256) {
        float4 x = hr[j], gg = g4[j], bb = b4[j];
        x.x = gelu_f((x.x - mean) * rs * gg.x + bb.x);
        x.y = gelu_f((x.y - mean) * rs * gg.y + bb.y);
        x.z = gelu_f((x.z - mean) * rs * gg.z + bb.z);
        x.w = gelu_f((x.w - mean) * rs * gg.w + bb.w);
        hr[j] = x;
    }
}

// ---------------- sigmoid head ----------------
__global__ void k_head(const float* __restrict__ hid, int K, const float* __restrict__ w,
                       const float* __restrict__ b, float* __restrict__ out,
                       float addc, int nanz) {
    if (g_done) return;
    int row = blockIdx.x, tid = threadIdx.x;
    float s = 0.f;
    for (int k = tid; k < K; k += 256) s = fmaf(hid[(size_t)row * K + k], w[k], s);
    __shared__ float sh[256];
    sh[tid] = s;
    __syncthreads();
    for (int o = 128; o > 0; o >>= 1) {
        if (tid < o) sh[tid] += sh[tid + o];
        __syncthreads();
    }
    if (tid == 0) {
        float v = 1.f / (1.f + expf(-(sh[0] + b[0])));
        if (nanz && isnan(v)) v = 0.f;
        out[row] = v + addc;
    }
}

// ---------------- update (float2 paths) ----------------
__global__ void k_update(const float* __restrict__ fd, const float* __restrict__ cs_p,
                         const float* __restrict__ ts_p) {
    if (g_done) return;
    int row = blockIdx.x, tid = threadIdx.x;
    float gam = g_gamma[row];
    float ac = gam * g_alpha_ct[2 * row] * (*cs_p);
    float at = gam * g_alpha_ct[2 * row + 1] * (*ts_p);
    const float2* ct_c = (const float2*)(g_ct + (size_t)row * F4);
    const float2* ct_t = (const float2*)(g_ct + (size_t)row * F4 + F2);
    const float2* fc2 = (const float2*)(g_fc + (size_t)row * F2);
    const float2* ft2 = (const float2*)(g_ft + (size_t)row * F2);
    float2* nw_c = (float2*)(g_new + (size_t)row * F4);
    float2* nw_t = (float2*)(g_new + (size_t)row * F4 + F2);
    float dc2 = 0.f, dt2 = 0.f, sc2 = 0.f, st2 = 0.f;
    for (int j2 = tid; j2 < 257; j2 += 256) {
        int j = 2 * j2;
        float fd0 = fd[j < NF ? j : j - NF];
        float fd1 = fd[(j + 1) < NF ? (j + 1) : (j + 1 - NF)];
        float2 c = ct_c[j2], f = fc2[j2];
        float2 nc;
        nc.x = fmaf(fd0, c.x, ac * f.x);
        nc.y = fmaf(fd1, c.y, ac * f.y);
        nw_c[j2] = nc;
        float d0 = nc.x - c.x, d1 = nc.y - c.y;
        dc2 += d0 * d0 + d1 * d1; sc2 += nc.x * nc.x + nc.y * nc.y;
        float2 t = ct_t[j2], ff = ft2[j2];
        float2 nt;
        nt.x = fmaf(fd0, t.x, at * ff.x);
        nt.y = fmaf(fd1, t.y, at * ff.y);
        nw_t[j2] = nt;
        d0 = nt.x - t.x; d1 = nt.y - t.y;
        dt2 += d0 * d0 + d1 * d1; st2 += nt.x * nt.x + nt.y * nt.y;
    }
    __shared__ float s0[256], s1[256], s2[256], s3[256];
    s0[tid] = dc2; s1[tid] = dt2; s2[tid] = sc2; s3[tid] = st2;
    __syncthreads();
    for (int o = 128; o > 0; o >>= 1) {
        if (tid < o) { s0[tid] += s0[tid + o]; s1[tid] += s1[tid + o];
                       s2[tid] += s2[tid + o]; s3[tid] += s3[tid + o]; }
        __syncthreads();
    }
    if (tid == 0) {
        g_rn_c[row] = sqrtf(s0[0]);
        g_rn_t[row] = sqrtf(s1[0]);
        g_sq_c[row] = s2[0];
        g_sq_t[row] = s3[0];
    }
}

// ---------------- reduce + convergence decision ----------------
__global__ void k_reduce_finalize() {
    __shared__ float4 sh[1024];
    int tid = threadIdx.x;
    float4 a = make_float4(0.f, 0.f, 0.f, 0.f);
    for (int i = tid; i < ROWS; i += 1024) {
        a.x += g_rn_c[i]; a.y += g_rn_t[i]; a.z += g_sq_c[i]; a.w += g_sq_t[i];
    }
    sh[tid] = a;
    __syncthreads();
    for (int o = 512; o > 0; o >>= 1) {
        if (tid < o) {
            sh[tid].x += sh[tid + o].x; sh[tid].y += sh[tid + o].y;
            sh[tid].z += sh[tid + o].z; sh[tid].w += sh[tid + o].w;
        }
        __syncthreads();
    }
    if (tid == 0) {
        if (g_done) {
            g_scal[2] = 0.f;
        } else {
            float dc = sh[0].x / (float)ROWS;
            float dt = sh[0].y / (float)ROWS;
            float nc = sqrtf(sh[0].z);
            float nt = sqrtf(sh[0].w);
            int conv = (dc < TOLV) && (dt < TOLV);
            g_scal[0] = conv ? 1.f : (nc > 10.f ? 10.f / nc : 1.f);
            g_scal[1] = conv ? 1.f : (nt > 10.f ? 10.f / nt : 1.f);
            g_scal[2] = 1.f;
            if (conv) g_done = 1;
        }
    }
}

// ---------------- apply (float2) ----------------
__global__ void k_apply() {
    if (g_scal[2] == 0.f) return;
    int idx = blockIdx.x * blockDim.x + threadIdx.x;
    if (idx >= ROWS * F4 / 2) return;
    int col = (2 * idx) % F4;
    float sc = (col < F2) ? g_scal[0] : g_scal[1];
    float2 v = ((const float2*)g_new)[idx];
    v.x *= sc; v.y *= sc;
    ((float2*)g_ct)[idx] = v;
}

// ---------------- host launch ----------------
extern "C" void kernel_launch(void* const* d_in, const int* in_sizes, int n_in,
                              void* d_out, int out_size) {
    const float* carrier = (const float*)d_in[0];
    const float* traj    = (const float*)d_in[1];
    const float* srcp    = (const float*)d_in[2];
    const float* tgtp    = (const float*)d_in[3];
    const float* cw1 = (const float*)d_in[4];
    const float* cb1 = (const float*)d_in[5];
    const float* cg  = (const float*)d_in[6];
    const float* cbe = (const float*)d_in[7];
    const float* cw2 = (const float*)d_in[8];
    const float* cb2 = (const float*)d_in[9];
    const float* tw1 = (const float*)d_in[10];
    const float* tb1 = (const float*)d_in[11];
    const float* tg_ = (const float*)d_in[12];
    const float* tbe = (const float*)d_in[13];
    const float* tw2 = (const float*)d_in[14];
    const float* tb2 = (const float*)d_in[15];
    const float* fd  = (const float*)d_in[16];
    const float* dw1 = (const float*)d_in[17];
    const float* db1 = (const float*)d_in[18];
    const float* dw2 = (const float*)d_in[19];
    const float* db2 = (const float*)d_in[20];
    const float* sw1 = (const float*)d_in[21];
    const float* sb1 = (const float*)d_in[22];
    const float* sw2 = (const float*)d_in[23];
    const float* sb2 = (const float*)d_in[24];
    const float* csc = (const float*)d_in[25];
    const float* tsc = (const float*)d_in[26];
    float* out = (float*)d_out;

    float *p_ct, *p_h, *p_fc, *p_ft, *p_hd, *p_hs;
    float *p_act, *p_gm, *p_bc, *p_bt, *p_Br, *p_Bi;
    __half *p_cw1T, *p_tw1T, *p_cw2T, *p_tw2T, *p_dw1T, *p_sw1T;
    cudaGetSymbolAddress((void**)&p_ct,  g_ct);
    cudaGetSymbolAddress((void**)&p_h,   g_h);
    cudaGetSymbolAddress((void**)&p_fc,  g_fc);
    cudaGetSymbolAddress((void**)&p_ft,  g_ft);
    cudaGetSymbolAddress((void**)&p_hd,  g_hd);
    cudaGetSymbolAddress((void**)&p_hs,  g_hs);
    cudaGetSymbolAddress((void**)&p_act, g_alpha_ct);
    cudaGetSymbolAddress((void**)&p_gm,  g_gamma);
    cudaGetSymbolAddress((void**)&p_bc,  g_base_c);
    cudaGetSymbolAddress((void**)&p_bt,  g_base_t);
    cudaGetSymbolAddress((void**)&p_Br,  g_Br);
    cudaGetSymbolAddress((void**)&p_Bi,  g_Bi);
    cudaGetSymbolAddress((void**)&p_cw1T, g_cw1T);
    cudaGetSymbolAddress((void**)&p_tw1T, g_tw1T);
    cudaGetSymbolAddress((void**)&p_cw2T, g_cw2T);
    cudaGetSymbolAddress((void**)&p_tw2T, g_tw2T);
    cudaGetSymbolAddress((void**)&p_dw1T, g_dw1T);
    cudaGetSymbolAddress((void**)&p_sw1T, g_sw1T);

    dim3 th(256);
    auto grid = [](int N, int M) { return dim3((N + 127) / 128, (M + 127) / 128); };

    // 0) tables + done reset
    k_init_tables<<<(SPATIAL * NF + 255) / 256, 256>>>();

    // 0b) weight transposes to fp16 K-major
    k_transpose_h<<<dim3((KP_F4 + 255) / 256, F4), th>>>(cw1, F4, F4, p_cw1T, KP_F4);
    k_transpose_h<<<dim3((KP_F4 + 255) / 256, F4), th>>>(tw1, F4, F4, p_tw1T, KP_F4);
    k_transpose_h<<<dim3((KP_F4 + 255) / 256, F2), th>>>(cw2, F4, F2, p_cw2T, KP_F4);
    k_transpose_h<<<dim3((KP_F4 + 255) / 256, F2), th>>>(tw2, F4, F2, p_tw2T, KP_F4);
    k_transpose_h<<<dim3((KP_F2 + 255) / 256, NF), th>>>(dw1, F2, NF, p_dw1T, KP_F2);
    k_transpose_h<<<dim3((KP_F2 + 255) / 256, FH), th>>>(sw1, F2, FH, p_sw1T, KP_F2);

    // 1) rfft as fp32 DFT-GEMM
    k_gemm<<<grid(F2, ROWS), th>>>(carrier, SPATIAL, p_Br, F2, p_ct, F4, ROWS, F2, SPATIAL);
    k_gemm<<<grid(F2, ROWS), th>>>(traj, SPATIAL, p_Br, F2, p_ct + F2, F4, ROWS, F2, SPATIAL);

    // 2) per-batch constant base
    dim3 bg((F4 + 31) / 32, BSZ);
    k_base<<<bg, th>>>(srcp, tgtp, cw1, cb1, p_bc);
    k_base<<<bg, th>>>(srcp, tgtp, tw1, tb1, p_bt);

    // 3) 20 fixed-point steps (fp16 tensor GEMMs)
    for (int s = 0; s < MAX_STEPS; s++) {
        // carrier freq-net
        k_gemm_h<<<grid(F4, ROWS), th>>>(p_ct, F4, p_cw1T, KP_F4, p_h, F4,
                                         ROWS, F4, F4, nullptr, p_bc, F4, 0, 0, 1);
        k_ln_gelu<<<ROWS, th>>>(p_h, cg, cbe);
        k_gemm_h<<<grid(F2, ROWS), th>>>(p_h, F4, p_cw2T, KP_F4, p_fc, F2,
                                         ROWS, F2, F4, cb2, nullptr, 0, 2, 0, 1);
        // trajectory freq-net
        k_gemm_h<<<grid(F4, ROWS), th>>>(p_ct, F4, p_tw1T, KP_F4, p_h, F4,
                                         ROWS, F4, F4, nullptr, p_bt, F4, 0, 0, 1);
        k_ln_gelu<<<ROWS, th>>>(p_h, tg_, tbe);
        k_gemm_h<<<grid(F2, ROWS), th>>>(p_h, F4, p_tw2T, KP_F4, p_ft, F2,
                                         ROWS, F2, F4, tb2, nullptr, 0, 2, 0, 1);
        // merged gating hidden (g_ct as [8192 x 514])
        k_gemm_h<<<grid(NF, 2 * ROWS), th>>>(p_ct, F2, p_dw1T, KP_F2, p_hd, NF,
                                             2 * ROWS, NF, F2, db1, nullptr, 0, 1, 1, 1);
        k_gemm_h<<<grid(FH, ROWS), th>>>(p_ct, F4, p_sw1T, KP_F2, p_hs, FH,
                                         ROWS, FH, F2, sb1, nullptr, 0, 1, 1, 1);
        // sigmoid heads
        k_head<<<2 * ROWS, th>>>(p_hd, NF, dw2, db2, p_act, 0.0f, 1);
        k_head<<<ROWS, th>>>(p_hs, FH, sw2, sb2, p_gm, 0.5f, 0);
        // update + convergence/clamp + commit
        k_update<<<ROWS, th>>>(fd, csc, tsc);
        k_reduce_finalize<<<1, 1024>>>();
        k_apply<<<(ROWS * F4 / 2 + 255) / 256, th>>>();
    }

    // 4) irfft as fp32 DFT-GEMM
    k_gemm<<<grid(SPATIAL, ROWS), th>>>(p_ct, F4, p_Bi, SPATIAL, out, SPATIAL,
                                        ROWS, SPATIAL, F2);
    k_gemm<<<grid(SPATIAL, ROWS), th>>>(p_ct + F2, F4, p_Bi, SPATIAL,
                                        out + (size_t)ROWS * SPATIAL, SPATIAL,
                                        ROWS, SPATIAL, F2);
    (void)in_sizes; (void)n_in; (void)out_size;
}

// round 5
// speedup vs baseline: 5.4820x; 1.5495x over previous
#include <cuda_runtime.h>
#include <cuda_fp16.h>
#include <math.h>
#include <stdint.h>

// ---------------- problem constants ----------------
#define BSZ 8
#define SEQ 512
#define ROWS 4096          // BSZ*SEQ
#define SPATIAL 512
#define NF 257             // rfft bins
#define F2 514
#define F4 1028
#define FH 128             // F//2
#define MAX_STEPS 20
#define TOLV 1e-3f
// padded GEMM dims
#define KW1 1088           // GEMM1 K: 2*544
#define NW1 2176           // GEMM1 N: 2056 -> 17 tiles
#define KW2 1056           // GEMM2 K: 1028 -> 33*32
#define NW2 640            // GEMM2 N: 514 -> 5 tiles
#define KD  544            // gating K: 514 -> 17*32
#define ND  384            // hd N: 257 -> 3 tiles
#define NBASE 2176

// ---------------- device scratch (static, zero-initialized) ----------------
__device__ float g_ct[ROWS * F4];          // fp32 state, row: [c(514) | t(514)]
__device__ float g_new[ROWS * F4];
__device__ float g_h[ROWS * 2056];         // merged GEMM1 output (c|t hiddens)
__device__ float g_fct[2 * ROWS * F2];     // rows 0..4095 fc, 4096.. ft
__device__ float g_hd[2 * ROWS * NF];      // rows 0..4095 c, 4096.. t
__device__ float g_hs[ROWS * FH];
__device__ float g_alpha[2 * ROWS];
__device__ float g_gamma[ROWS];
__device__ float g_base[BSZ * NBASE];      // cols 0..1027 c-base, 1028..2055 t-base
__device__ float g_rn_c[ROWS], g_rn_t[ROWS], g_sq_c[ROWS], g_sq_t[ROWS];
__device__ float g_scal[4];
__device__ int   g_done;
__device__ float g_Br[SPATIAL * F2];
__device__ float g_Bi[F2 * SPATIAL];
// fp16 activations (pads stay zero — never written)
__device__ __half g_ct_h[2 * ROWS * KD];   // rows 0..4095 = c(514 + pad), 4096.. = t
__device__ __half g_h_h[2 * ROWS * KW2];   // rows 0..4095 = c-hidden, 4096.. = t-hidden
// fp16 K-major transposed weights (pads stay zero)
__device__ __half g_w1T[NW1 * KW1];        // n<1028 cw1, n in [1028,2056) tw1
__device__ __half g_cw2T[NW2 * KW2];
__device__ __half g_tw2T[NW2 * KW2];
__device__ __half g_dw1T[ND * KD];
__device__ __half g_sw1T[FH * KD];

// ---------------- helpers ----------------
__device__ __forceinline__ float gelu_f(float x) {
    return 0.5f * x * (1.0f + erff(x * 0.70710678118654752f));
}
__device__ __forceinline__ uint32_t smem_u32(const void* p) {
    uint32_t a;
    asm("{ .reg .u64 t; cvta.to.shared.u64 t, %1; cvt.u32.u64 %0, t; }" : "=r"(a) : "l"(p));
    return a;
}
__device__ __forceinline__ void cp8(uint32_t dst, const void* src) {
    asm volatile("cp.async.ca.shared.global [%0], [%1], 8;" :: "r"(dst), "l"(src));
}

// ---------------- table init ----------------
__global__ void k_init_tables() {
    int idx = blockIdx.x * blockDim.x + threadIdx.x;
    if (idx == 0) g_done = 0;
    int total = SPATIAL * NF;
    if (idx >= total) return;
    int n = idx / NF, k = idx % NF;
    double r = (double)((k * n) & 511) / 256.0;
    double sv, cv;
    sincospi(r, &sv, &cv);
    g_Br[n * F2 + 2 * k]     = (float)cv;
    g_Br[n * F2 + 2 * k + 1] = (float)(-sv);
    double w = (k == 0 || k == NF - 1) ? 1.0 : 2.0;
    g_Bi[(2 * k) * SPATIAL + n]     = (float)(w * cv / 512.0);
    g_Bi[(2 * k + 1) * SPATIAL + n] = (float)(-w * sv / 512.0);
}

// ---------------- generic transpose: WT[(n_off+n)*ldk + k_off + k] = W[k][n] ----------------
__global__ void k_tr(const float* __restrict__ W, int K, int N,
                     __half* __restrict__ WT, int ldk, int n_off, int k_off) {
    int k = blockIdx.x * 256 + threadIdx.x;
    int n = blockIdx.y;
    if (k >= K) return;
    WT[(size_t)(n_off + n) * ldk + k_off + k] = __float2half_rn(W[(size_t)k * N + n]);
}

// =====================================================================
// FP16 tensor GEMM with cp.async 2-stage pipeline.
// C[M,N] = act(A @ BT^T + bias + base).  All operands fp16 in gmem,
// K padded (nkb*32), M multiple of 128, B buffers padded to tile N.
// A split along K: kblocks < kb_lo from A_lo, rest from A_hi.
// B/bias selected per row tile: row0 < M_lo -> lo else hi.
// =====================================================================
__global__ __launch_bounds__(256) void k_gemm_h(
    const __half* __restrict__ A_lo, const __half* __restrict__ A_hi,
    int ldaH, int kb_lo,
    const __half* __restrict__ B_lo, const __half* __restrict__ B_hi,
    int ldbH, int M_lo,
    float* __restrict__ C, int ldc, int M, int N, int nkb,
    const float* __restrict__ bias_lo, const float* __restrict__ bias_hi,
    const float* __restrict__ base, int base_ld,
    int act, int chk) {
    if (chk && g_done) return;

    __shared__ __half As[2][128][40];
    __shared__ __half Bs[2][128][40];

    const int tid = threadIdx.x;
    const int warp = tid >> 5, lane = tid & 31;
    const int gid = lane >> 2, tg = lane & 3;
    const int wm = warp & 1, wn = warp >> 1;
    const int row0 = blockIdx.y * 128, col0 = blockIdx.x * 128;

    const __half* BT = (row0 < M_lo) ? B_lo : B_hi;
    const float* bias = (row0 < M_lo) ? bias_lo : bias_hi;

    float acc[4][4][4];
#pragma unroll
    for (int mi = 0; mi < 4; mi++)
#pragma unroll
        for (int ni = 0; ni < 4; ni++)
#pragma unroll
            for (int q = 0; q < 4; q++) acc[mi][ni][q] = 0.f;

    const uint32_t sA = smem_u32(As), sB = smem_u32(Bs);
    const int rr = tid >> 3;            // 0..31 (+ i*32)
    const int c8 = tid & 7;             // 8B chunk in 64B row

    auto issue = [&](int kb, int buf) {
        const __half* Ab;
        int kk;
        if (kb < kb_lo) { Ab = A_lo; kk = kb * 32; }
        else            { Ab = A_hi; kk = (kb - kb_lo) * 32; }
        uint32_t dA = sA + buf * 10240u + rr * 80u + c8 * 8u;
        const __half* gA = Ab + (size_t)(row0 + rr) * ldaH + kk + c8 * 4;
#pragma unroll
        for (int i = 0; i < 4; i++)
            cp8(dA + i * 32 * 80u, gA + (size_t)i * 32 * ldaH);
        uint32_t dB = sB + buf * 10240u + rr * 80u + c8 * 8u;
        const __half* gB = BT + (size_t)(col0 + rr) * ldbH + kb * 32 + c8 * 4;
#pragma unroll
        for (int i = 0; i < 4; i++)
            cp8(dB + i * 32 * 80u, gB + (size_t)i * 32 * ldbH);
        asm volatile("cp.async.commit_group;" ::: "memory");
    };

    issue(0, 0);
    for (int kb = 0; kb < nkb; kb++) {
        int buf = kb & 1;
        if (kb + 1 < nkb) {
            issue(kb + 1, buf ^ 1);
            asm volatile("cp.async.wait_group 1;" ::: "memory");
        } else {
            asm volatile("cp.async.wait_group 0;" ::: "memory");
        }
        __syncthreads();
#pragma unroll
        for (int s = 0; s < 2; s++) {
            uint32_t af[4][4], bf[4][2];
#pragma unroll
            for (int mi = 0; mi < 4; mi++) {
                int m = wm * 64 + mi * 16 + gid;
                af[mi][0] = *(const uint32_t*)&As[buf][m][s * 16 + 2 * tg];
                af[mi][1] = *(const uint32_t*)&As[buf][m + 8][s * 16 + 2 * tg];
                af[mi][2] = *(const uint32_t*)&As[buf][m][s * 16 + 2 * tg + 8];
                af[mi][3] = *(const uint32_t*)&As[buf][m + 8][s * 16 + 2 * tg + 8];
            }
#pragma unroll
            for (int ni = 0; ni < 4; ni++) {
                int n = wn * 32 + ni * 8 + gid;
                bf[ni][0] = *(const uint32_t*)&Bs[buf][n][s * 16 + 2 * tg];
                bf[ni][1] = *(const uint32_t*)&Bs[buf][n][s * 16 + 2 * tg + 8];
            }
#pragma unroll
            for (int mi = 0; mi < 4; mi++)
#pragma unroll
                for (int ni = 0; ni < 4; ni++) {
                    asm volatile(
                        "mma.sync.aligned.m16n8k16.row.col.f32.f16.f16.f32 "
                        "{%0,%1,%2,%3}, {%4,%5,%6,%7}, {%8,%9}, {%0,%1,%2,%3};"
                        : "+f"(acc[mi][ni][0]), "+f"(acc[mi][ni][1]),
                          "+f"(acc[mi][ni][2]), "+f"(acc[mi][ni][3])
                        : "r"(af[mi][0]), "r"(af[mi][1]), "r"(af[mi][2]), "r"(af[mi][3]),
                          "r"(bf[ni][0]), "r"(bf[ni][1]));
                }
        }
        __syncthreads();
    }

    // epilogue
#pragma unroll
    for (int mi = 0; mi < 4; mi++) {
#pragma unroll
        for (int ni = 0; ni < 4; ni++) {
#pragma unroll
            for (int q = 0; q < 4; q++) {
                int r = row0 + wm * 64 + mi * 16 + gid + (q >> 1) * 8;
                int c = col0 + wn * 32 + ni * 8 + tg * 2 + (q & 1);
                if (r >= M || c >= N) continue;
                float v = acc[mi][ni][q];
                if (bias) v += bias[c];
                if (base) v += base[(r >> 9) * base_ld + c];
                if (act == 1) v = gelu_f(v);
                else if (act == 2) v = tanhf(v);
                C[(size_t)r * ldc + c] = v;
            }
        }
    }
}

// ---------------- fp32 SGEMM (FFT transforms only) ----------------
__global__ void k_gemm(const float* __restrict__ A, int lda,
                       const float* __restrict__ B, int ldb,
                       float* __restrict__ C, int ldc,
                       int M, int N, int K) {
    __shared__ float As[8][128];
    __shared__ float Bs[8][128];
    int tid = threadIdx.x;
    int row0 = blockIdx.y * 128, col0 = blockIdx.x * 128;
    int ty = tid >> 4, tx = tid & 15;
    int ar = tid >> 1, ac = (tid & 1) * 4;
    int br = tid >> 5, bc = (tid & 31) * 4;
    float acc[8][8];
#pragma unroll
    for (int i = 0; i < 8; i++)
#pragma unroll
        for (int j = 0; j < 8; j++) acc[i][j] = 0.f;
    for (int k0 = 0; k0 < K; k0 += 8) {
        int gr = row0 + ar;
#pragma unroll
        for (int u = 0; u < 4; u++) {
            int gk = k0 + ac + u;
            As[ac + u][ar] = (gr < M && gk < K) ? A[(size_t)gr * lda + gk] : 0.f;
        }
        int gk = k0 + br;
#pragma unroll
        for (int u = 0; u < 4; u++) {
            int gc = col0 + bc + u;
            Bs[br][bc + u] = (gk < K && gc < N) ? B[(size_t)gk * ldb + gc] : 0.f;
        }
        __syncthreads();
#pragma unroll
        for (int kk = 0; kk < 8; kk++) {
            float a_[8], b_[8];
#pragma unroll
            for (int i = 0; i < 8; i++) a_[i] = As[kk][ty * 8 + i];
#pragma unroll
            for (int j = 0; j < 8; j++) b_[j] = Bs[kk][tx * 8 + j];
#pragma unroll
            for (int i = 0; i < 8; i++)
#pragma unroll
                for (int j = 0; j < 8; j++)
                    acc[i][j] = fmaf(a_[i], b_[j], acc[i][j]);
        }
        __syncthreads();
    }
#pragma unroll
    for (int i = 0; i < 8; i++) {
        int r = row0 + ty * 8 + i;
        if (r >= M) continue;
#pragma unroll
        for (int j = 0; j < 8; j++) {
            int c = col0 + tx * 8 + j;
            if (c < N) C[(size_t)r * ldc + c] = acc[i][j];
        }
    }
}

// ---------------- per-batch constant base ----------------
__global__ void k_base(const float* __restrict__ src, const float* __restrict__ tgt,
                       const float* __restrict__ w1, const float* __restrict__ b1,
                       int out_off) {
    int b = blockIdx.y;
    int tid = threadIdx.x;
    int jj = tid & 31;
    int ks = tid >> 5;
    int j = blockIdx.x * 32 + jj;
    float s = 0.f;
    if (j < F4) {
        const float* ps = src + b * 513;
        const float* pt = tgt + b * 513;
        for (int k = ks * 128; k < ks * 128 + 128; k++) {
            float x = (k < 512) ? ps[k] : pt[k - 512];
            s = fmaf(x, w1[(size_t)(F4 + k) * F4 + j], s);
        }
    }
    __shared__ float sh[8][32];
    sh[ks][jj] = s;
    __syncthreads();
    if (ks == 0 && j < F4) {
        float t = b1[j];
#pragma unroll
        for (int q = 0; q < 8; q++) t += sh[q][jj];
        g_base[b * NBASE + out_off + j] = t;
    }
}

// ---------------- rfft output -> fp16 state copy ----------------
__global__ void k_convert() {
    int r = blockIdx.x, tid = threadIdx.x;
    const float2* sc = (const float2*)(g_ct + (size_t)r * F4);
    const float2* st = (const float2*)(g_ct + (size_t)r * F4 + F2);
    __half2* dc = (__half2*)(g_ct_h + (size_t)r * KD);
    __half2* dt = (__half2*)(g_ct_h + (size_t)(ROWS + r) * KD);
    for (int j = tid; j < 257; j += 256) {
        dc[j] = __float22half2_rn(sc[j]);
        dt[j] = __float22half2_rn(st[j]);
    }
}

// ---------------- LayerNorm + exact GELU -> fp16 hidden ----------------
__global__ void k_ln_gelu(const float* __restrict__ gc, const float* __restrict__ bc,
                          const float* __restrict__ gt, const float* __restrict__ bt) {
    if (g_done) return;
    int r = blockIdx.x, h = blockIdx.y, tid = threadIdx.x;
    const float* g = h ? gt : gc;
    const float* be = h ? bt : bc;
    const float4* hr = (const float4*)(g_h + (size_t)r * 2056 + h * 1028);  // 257 float4
    __half2* out = (__half2*)(g_h_h + (size_t)(h * ROWS + r) * KW2);
    float s = 0.f, s2 = 0.f;
    for (int j = tid; j < 257; j += 256) {
        float4 x = hr[j];
        s += x.x + x.y + x.z + x.w;
        s2 += x.x * x.x + x.y * x.y + x.z * x.z + x.w * x.w;
    }
    __shared__ float sa[256], sb[256];
    sa[tid] = s; sb[tid] = s2;
    __syncthreads();
    for (int o = 128; o > 0; o >>= 1) {
        if (tid < o) { sa[tid] += sa[tid + o]; sb[tid] += sb[tid + o]; }
        __syncthreads();
    }
    float mean = sa[0] / F4;
    float var = sb[0] / F4 - mean * mean;
    float rs = rsqrtf(var + 1e-5f);
    const float4* g4 = (const float4*)g;
    const float4* b4 = (const float4*)be;
    for (int j = tid; j < 257; j += 256) {
        float4 x = hr[j], gg = g4[j], bb = b4[j];
        float2 lo, hi;
        lo.x = gelu_f((x.x - mean) * rs * gg.x + bb.x);
        lo.y = gelu_f((x.y - mean) * rs * gg.y + bb.y);
        hi.x = gelu_f((x.z - mean) * rs * gg.z + bb.z);
        hi.y = gelu_f((x.w - mean) * rs * gg.w + bb.w);
        out[2 * j] = __float22half2_rn(lo);
        out[2 * j + 1] = __float22half2_rn(hi);
    }
}

// ---------------- sigmoid head ----------------
__global__ void k_head(const float* __restrict__ hid, int K, const float* __restrict__ w,
                       const float* __restrict__ b, float* __restrict__ out,
                       float addc, int nanz) {
    if (g_done) return;
    int row = blockIdx.x, tid = threadIdx.x;
    float s = 0.f;
    for (int k = tid; k < K; k += 256) s = fmaf(hid[(size_t)row * K + k], w[k], s);
    __shared__ float sh[256];
    sh[tid] = s;
    __syncthreads();
    for (int o = 128; o > 0; o >>= 1) {
        if (tid < o) sh[tid] += sh[tid + o];
        __syncthreads();
    }
    if (tid == 0) {
        float v = 1.f / (1.f + expf(-(sh[0] + b[0])));
        if (nanz && isnan(v)) v = 0.f;
        out[row] = v + addc;
    }
}

// ---------------- update: new = damping*old + gamma*alpha*scale*f ----------------
__global__ void k_update(const float* __restrict__ fd, const float* __restrict__ cs_p,
                         const float* __restrict__ ts_p) {
    if (g_done) return;
    int row = blockIdx.x, tid = threadIdx.x;
    float gam = g_gamma[row];
    float ac = gam * g_alpha[row] * (*cs_p);
    float at = gam * g_alpha[ROWS + row] * (*ts_p);
    const float2* ct_c = (const float2*)(g_ct + (size_t)row * F4);
    const float2* ct_t = (const float2*)(g_ct + (size_t)row * F4 + F2);
    const float2* fc2 = (const float2*)(g_fct + (size_t)row * F2);
    const float2* ft2 = (const float2*)(g_fct + (size_t)(ROWS + row) * F2);
    float2* nw_c = (float2*)(g_new + (size_t)row * F4);
    float2* nw_t = (float2*)(g_new + (size_t)row * F4 + F2);
    float dc2 = 0.f, dt2 = 0.f, sc2 = 0.f, st2 = 0.f;
    for (int j2 = tid; j2 < 257; j2 += 256) {
        int j = 2 * j2;
        float fd0 = fd[j < NF ? j : j - NF];
        float fd1 = fd[(j + 1) < NF ? (j + 1) : (j + 1 - NF)];
        float2 c = ct_c[j2], f = fc2[j2];
        float2 nc;
        nc.x = fmaf(fd0, c.x, ac * f.x);
        nc.y = fmaf(fd1, c.y, ac * f.y);
        nw_c[j2] = nc;
        float d0 = nc.x - c.x, d1 = nc.y - c.y;
        dc2 += d0 * d0 + d1 * d1; sc2 += nc.x * nc.x + nc.y * nc.y;
        float2 t = ct_t[j2], ff = ft2[j2];
        float2 nt;
        nt.x = fmaf(fd0, t.x, at * ff.x);
        nt.y = fmaf(fd1, t.y, at * ff.y);
        nw_t[j2] = nt;
        d0 = nt.x - t.x; d1 = nt.y - t.y;
        dt2 += d0 * d0 + d1 * d1; st2 += nt.x * nt.x + nt.y * nt.y;
    }
    __shared__ float s0[256], s1[256], s2[256], s3[256];
    s0[tid] = dc2; s1[tid] = dt2; s2[tid] = sc2; s3[tid] = st2;
    __syncthreads();
    for (int o = 128; o > 0; o >>= 1) {
        if (tid < o) { s0[tid] += s0[tid + o]; s1[tid] += s1[tid + o];
                       s2[tid] += s2[tid + o]; s3[tid] += s3[tid + o]; }
        __syncthreads();
    }
    if (tid == 0) {
        g_rn_c[row] = sqrtf(s0[0]);
        g_rn_t[row] = sqrtf(s1[0]);
        g_sq_c[row] = s2[0];
        g_sq_t[row] = s3[0];
    }
}

// ---------------- reduce + convergence decision ----------------
__global__ void k_reduce_finalize() {
    __shared__ float4 sh[1024];
    int tid = threadIdx.x;
    float4 a = make_float4(0.f, 0.f, 0.f, 0.f);
    for (int i = tid; i < ROWS; i += 1024) {
        a.x += g_rn_c[i]; a.y += g_rn_t[i]; a.z += g_sq_c[i]; a.w += g_sq_t[i];
    }
    sh[tid] = a;
    __syncthreads();
    for (int o = 512; o > 0; o >>= 1) {
        if (tid < o) {
            sh[tid].x += sh[tid + o].x; sh[tid].y += sh[tid + o].y;
            sh[tid].z += sh[tid + o].z; sh[tid].w += sh[tid + o].w;
        }
        __syncthreads();
    }
    if (tid == 0) {
        if (g_done) {
            g_scal[2] = 0.f;
        } else {
            float dc = sh[0].x / (float)ROWS;
            float dt = sh[0].y / (float)ROWS;
            float nc = sqrtf(sh[0].z);
            float nt = sqrtf(sh[0].w);
            int conv = (dc < TOLV) && (dt < TOLV);
            g_scal[0] = conv ? 1.f : (nc > 10.f ? 10.f / nc : 1.f);
            g_scal[1] = conv ? 1.f : (nt > 10.f ? 10.f / nt : 1.f);
            g_scal[2] = 1.f;
            if (conv) g_done = 1;
        }
    }
}

// ---------------- apply: commit state (fp32 + fp16 copies) ----------------
__global__ void k_apply() {
    if (g_scal[2] == 0.f) return;
    int r = blockIdx.x, tid = threadIdx.x;
    float sc = g_scal[0], st = g_scal[1];
    const float2* nw = (const float2*)(g_new + (size_t)r * F4);
    float2* ct = (float2*)(g_ct + (size_t)r * F4);
    __half2* hc = (__half2*)(g_ct_h + (size_t)r * KD);
    __half2* ht = (__half2*)(g_ct_h + (size_t)(ROWS + r) * KD);
    for (int j = tid; j < 257; j += 256) {
        float2 v = nw[j];
        v.x *= sc; v.y *= sc;
        ct[j] = v;
        hc[j] = __float22half2_rn(v);
        float2 w = nw[257 + j];
        w.x *= st; w.y *= st;
        ct[257 + j] = w;
        ht[j] = __float22half2_rn(w);
    }
}

// ---------------- host launch ----------------
extern "C" void kernel_launch(void* const* d_in, const int* in_sizes, int n_in,
                              void* d_out, int out_size) {
    const float* carrier = (const float*)d_in[0];
    const float* traj    = (const float*)d_in[1];
    const float* srcp    = (const float*)d_in[2];
    const float* tgtp    = (const float*)d_in[3];
    const float* cw1 = (const float*)d_in[4];
    const float* cb1 = (const float*)d_in[5];
    const float* cg  = (const float*)d_in[6];
    const float* cbe = (const float*)d_in[7];
    const float* cw2 = (const float*)d_in[8];
    const float* cb2 = (const float*)d_in[9];
    const float* tw1 = (const float*)d_in[10];
    const float* tb1 = (const float*)d_in[11];
    const float* tg_ = (const float*)d_in[12];
    const float* tbe = (const float*)d_in[13];
    const float* tw2 = (const float*)d_in[14];
    const float* tb2 = (const float*)d_in[15];
    const float* fd  = (const float*)d_in[16];
    const float* dw1 = (const float*)d_in[17];
    const float* db1 = (const float*)d_in[18];
    const float* dw2 = (const float*)d_in[19];
    const float* db2 = (const float*)d_in[20];
    const float* sw1 = (const float*)d_in[21];
    const float* sb1 = (const float*)d_in[22];
    const float* sw2 = (const float*)d_in[23];
    const float* sb2 = (const float*)d_in[24];
    const float* csc = (const float*)d_in[25];
    const float* tsc = (const float*)d_in[26];
    float* out = (float*)d_out;

    float *p_ct, *p_h, *p_fct, *p_hd, *p_hs, *p_alpha, *p_gm, *p_Br, *p_Bi;
    __half *p_ct_h, *p_h_h, *p_w1T, *p_cw2T, *p_tw2T, *p_dw1T, *p_sw1T;
    cudaGetSymbolAddress((void**)&p_ct,   g_ct);
    cudaGetSymbolAddress((void**)&p_h,    g_h);
    cudaGetSymbolAddress((void**)&p_fct,  g_fct);
    cudaGetSymbolAddress((void**)&p_hd,   g_hd);
    cudaGetSymbolAddress((void**)&p_hs,   g_hs);
    cudaGetSymbolAddress((void**)&p_alpha,g_alpha);
    cudaGetSymbolAddress((void**)&p_gm,   g_gamma);
    cudaGetSymbolAddress((void**)&p_Br,   g_Br);
    cudaGetSymbolAddress((void**)&p_Bi,   g_Bi);
    cudaGetSymbolAddress((void**)&p_ct_h, g_ct_h);
    cudaGetSymbolAddress((void**)&p_h_h,  g_h_h);
    cudaGetSymbolAddress((void**)&p_w1T,  g_w1T);
    cudaGetSymbolAddress((void**)&p_cw2T, g_cw2T);
    cudaGetSymbolAddress((void**)&p_tw2T, g_tw2T);
    cudaGetSymbolAddress((void**)&p_dw1T, g_dw1T);
    cudaGetSymbolAddress((void**)&p_sw1T, g_sw1T);
    float* p_base;
    cudaGetSymbolAddress((void**)&p_base, g_base);

    dim3 th(256);
    auto grid = [](int N, int M) { return dim3((N + 127) / 128, (M + 127) / 128); };

    // 0) tables + done reset
    k_init_tables<<<(SPATIAL * NF + 255) / 256, 256>>>();

    // 0b) weight transposes (pads stay zero via static zero-init)
    k_tr<<<dim3(3, 1028), th>>>(cw1, 514, F4, p_w1T, KW1, 0, 0);
    k_tr<<<dim3(3, 1028), th>>>(cw1 + (size_t)514 * F4, 514, F4, p_w1T, KW1, 0, 544);
    k_tr<<<dim3(3, 1028), th>>>(tw1, 514, F4, p_w1T, KW1, 1028, 0);
    k_tr<<<dim3(3, 1028), th>>>(tw1 + (size_t)514 * F4, 514, F4, p_w1T, KW1, 1028, 544);
    k_tr<<<dim3(5, 514), th>>>(cw2, F4, F2, p_cw2T, KW2, 0, 0);
    k_tr<<<dim3(5, 514), th>>>(tw2, F4, F2, p_tw2T, KW2, 0, 0);
    k_tr<<<dim3(3, 257), th>>>(dw1, F2, NF, p_dw1T, KD, 0, 0);
    k_tr<<<dim3(3, 128), th>>>(sw1, F2, FH, p_sw1T, KD, 0, 0);

    // 1) rfft as fp32 DFT-GEMM, then fp16 state copy
    k_gemm<<<grid(F2, ROWS), th>>>(carrier, SPATIAL, p_Br, F2, p_ct, F4, ROWS, F2, SPATIAL);
    k_gemm<<<grid(F2, ROWS), th>>>(traj, SPATIAL, p_Br, F2, p_ct + F2, F4, ROWS, F2, SPATIAL);
    k_convert<<<ROWS, th>>>();

    // 2) per-batch constant base (c cols 0..1027, t cols 1028..2055)
    dim3 bg((F4 + 31) / 32, BSZ);
    k_base<<<bg, th>>>(srcp, tgtp, cw1, cb1, 0);
    k_base<<<bg, th>>>(srcp, tgtp, tw1, tb1, 1028);

    // 3) 20 fixed-point steps
    for (int s = 0; s < MAX_STEPS; s++) {
        // merged freq-net GEMM1: [4096 x 2056]
        k_gemm_h<<<grid(2056, ROWS), th>>>(
            p_ct_h, p_ct_h + (size_t)ROWS * KD, KD, 17,
            p_w1T, p_w1T, KW1, ROWS,
            p_h, 2056, ROWS, 2056, KW1 / 32,
            nullptr, nullptr, p_base, NBASE, 0, 1);
        // LN + GELU -> fp16 hidden
        k_ln_gelu<<<dim3(ROWS, 2), th>>>(cg, cbe, tg_, tbe);
        // merged GEMM2: [8192 x 514], weight per row half
        k_gemm_h<<<grid(F2, 2 * ROWS), th>>>(
            p_h_h, p_h_h, KW2, KW2 / 32,
            p_cw2T, p_tw2T, KW2, ROWS,
            p_fct, F2, 2 * ROWS, F2, KW2 / 32,
            cb2, tb2, nullptr, 0, 2, 1);
        // gating hiddens
        k_gemm_h<<<grid(NF, 2 * ROWS), th>>>(
            p_ct_h, p_ct_h, KD, KD / 32,
            p_dw1T, p_dw1T, KD, 2 * ROWS,
            p_hd, NF, 2 * ROWS, NF, KD / 32,
            db1, db1, nullptr, 0, 1, 1);
        k_gemm_h<<<grid(FH, ROWS), th>>>(
            p_ct_h, p_ct_h, KD, KD / 32,
            p_sw1T, p_sw1T, KD, ROWS,
            p_hs, FH, ROWS, FH, KD / 32,
            sb1, sb1, nullptr, 0, 1, 1);
        // heads
        k_head<<<2 * ROWS, th>>>(p_hd, NF, dw2, db2, p_alpha, 0.0f, 1);
        k_head<<<ROWS, th>>>(p_hs, FH, sw2, sb2, p_gm, 0.5f, 0);
        // update + convergence + commit
        k_update<<<ROWS, th>>>(fd, csc, tsc);
        k_reduce_finalize<<<1, 1024>>>();
        k_apply<<<ROWS, th>>>();
    }

    // 4) irfft as fp32 DFT-GEMM
    k_gemm<<<grid(SPATIAL, ROWS), th>>>(p_ct, F4, p_Bi, SPATIAL, out, SPATIAL,
                                        ROWS, SPATIAL, F2);
    k_gemm<<<grid(SPATIAL, ROWS), th>>>(p_ct + F2, F4, p_Bi, SPATIAL,
                                        out + (size_t)ROWS * SPATIAL, SPATIAL,
                                        ROWS, SPATIAL, F2);
    (void)in_sizes; (void)n_in; (void)out_size;
}

// round 8
// speedup vs baseline: 6.1929x; 1.1297x over previous
#include <cuda_runtime.h>
#include <cuda_fp16.h>
#include <math.h>
#include <stdint.h>

// ---------------- problem constants ----------------
#define BSZ 8
#define SEQ 512
#define ROWS 4096          // BSZ*SEQ
#define SPATIAL 512
#define NF 257             // rfft bins
#define F2 514
#define F4 1028
#define FH 128             // F//2
#define MAX_STEPS 20
#define TOLV 1e-3f
// padded GEMM dims
#define KW1 1088           // GEMM1 K: 2*544
#define NW1 2176           // GEMM1 N rows in w1T
#define KW2 1056           // GEMM2 K
#define NW2 640            // GEMM2 N rows in w2T
#define KD  544            // gating K
#define NG  385            // gating N: 257 hd + 128 hs
#define NGP 512            // gating B rows (padded)
#define NBASE 2176
// GEMM smem: 4 stages x (A 128x40 + B 128x40) halfs
#define STAGE_H 10240      // halfs per stage
#define STAGE_B 20480      // bytes per stage
#define SMEM_BYTES (4 * STAGE_B)

// ---------------- device scratch (static, zero-initialized) ----------------
__device__ float g_ct[ROWS * F4];          // fp32 state, row: [c(514) | t(514)]
__device__ float g_new[ROWS * F4];
__device__ float g_h[ROWS * 2056];         // merged GEMM1 output
__device__ float g_fct[2 * ROWS * F2];     // rows 0..4095 fc, 4096.. ft
__device__ float g_g[2 * ROWS * 512];      // gating hidden: cols 0..256 hd, 257..384 hs
__device__ float g_base[BSZ * NBASE];
__device__ float g_gbias[NGP];
__device__ float g_rn_c[ROWS], g_rn_t[ROWS], g_sq_c[ROWS], g_sq_t[ROWS];
__device__ float g_scal[4];
__device__ int   g_done;
__device__ float g_Br[SPATIAL * F2];
__device__ float g_Bi[F2 * SPATIAL];
// fp16 activations (pads never written -> stay zero)
__device__ __half g_ct_h[2 * ROWS * KD];
__device__ __half g_h_h[2 * ROWS * KW2];
// fp16 K-major weights (pads stay zero)
__device__ __half g_w1T[NW1 * KW1];
__device__ __half g_cw2T[NW2 * KW2];
__device__ __half g_tw2T[NW2 * KW2];
__device__ __half g_gwT[NGP * KD];         // rows 0..256 dw1T, 257..384 sw1T

// ---------------- helpers ----------------
__device__ __forceinline__ float gelu_f(float x) {
    return 0.5f * x * (1.0f + erff(x * 0.70710678118654752f));
}
__device__ __forceinline__ uint32_t smem_u32(const void* p) {
    uint32_t a;
    asm("{ .reg .u64 t; cvta.to.shared.u64 t, %1; cvt.u32.u64 %0, t; }" : "=r"(a) : "l"(p));
    return a;
}
__device__ __forceinline__ void cp8(uint32_t dst, const void* src) {
    asm volatile("cp.async.ca.shared.global [%0], [%1], 8;" :: "r"(dst), "l"(src));
}

// ---------------- table init ----------------
__global__ void k_init_tables() {
    int idx = blockIdx.x * blockDim.x + threadIdx.x;
    if (idx == 0) g_done = 0;
    int total = SPATIAL * NF;
    if (idx >= total) return;
    int n = idx / NF, k = idx % NF;
    double r = (double)((k * n) & 511) / 256.0;
    double sv, cv;
    sincospi(r, &sv, &cv);
    g_Br[n * F2 + 2 * k]     = (float)cv;
    g_Br[n * F2 + 2 * k + 1] = (float)(-sv);
    double w = (k == 0 || k == NF - 1) ? 1.0 : 2.0;
    g_Bi[(2 * k) * SPATIAL + n]     = (float)(w * cv / 512.0);
    g_Bi[(2 * k + 1) * SPATIAL + n] = (float)(-w * sv / 512.0);
}

// ---------------- transpose W[k][n] -> WT[(n_off+n)*ldk + k] fp16 ----------------
__global__ void k_tr(const float* __restrict__ W, int K, int N,
                     __half* __restrict__ WT, int ldk, int n_off) {
    int k = blockIdx.x * 256 + threadIdx.x;
    int n = blockIdx.y;
    if (k >= K) return;
    WT[(size_t)(n_off + n) * ldk + k] = __float2half_rn(W[(size_t)k * N + n]);
}

// ---------------- gating bias concat ----------------
__global__ void k_gbias(const float* __restrict__ db1, const float* __restrict__ sb1) {
    int i = threadIdx.x + blockIdx.x * 256;
    if (i >= NGP) return;
    g_gbias[i] = (i < 257) ? db1[i] : (i < NG ? sb1[i - 257] : 0.f);
}

// =====================================================================
// FP16 tensor GEMM, 4-stage cp.async pipeline, one sync per K-block.
// C[M,N] = act(A @ BT^T + bias + base).
// A split along K: kblocks < kb_lo from A_lo else A_hi.
// B/bias per row tile: row0 < M_lo -> lo else hi.
// =====================================================================
__global__ __launch_bounds__(256) void k_gemm_h(
    const __half* __restrict__ A_lo, const __half* __restrict__ A_hi,
    int ldaH, int kb_lo,
    const __half* __restrict__ B_lo, const __half* __restrict__ B_hi,
    int ldbH, int M_lo,
    float* __restrict__ C, int ldc, int M, int N, int nkb,
    const float* __restrict__ bias_lo, const float* __restrict__ bias_hi,
    const float* __restrict__ base, int base_ld,
    int act, int chk) {
    if (chk && g_done) return;
    extern __shared__ __half dyn[];

    const int tid = threadIdx.x;
    const int warp = tid >> 5, lane = tid & 31;
    const int gid = lane >> 2, tg = lane & 3;
    const int wm = warp & 1, wn = warp >> 1;
    const int row0 = blockIdx.y * 128, col0 = blockIdx.x * 128;

    const __half* BT = (row0 < M_lo) ? B_lo : B_hi;
    const float* bias = (row0 < M_lo) ? bias_lo : bias_hi;

    float acc[4][4][4];
#pragma unroll
    for (int mi = 0; mi < 4; mi++)
#pragma unroll
        for (int ni = 0; ni < 4; ni++)
#pragma unroll
            for (int q = 0; q < 4; q++) acc[mi][ni][q] = 0.f;

    const uint32_t sbase = smem_u32(dyn);
    const int rr = tid >> 3;            // 0..31 (+ i*32)
    const int c8 = tid & 7;

    auto issue = [&](int kb) {
        int buf = kb & 3;
        const __half* Ab;
        int kk;
        if (kb < kb_lo) { Ab = A_lo; kk = kb * 32; }
        else            { Ab = A_hi; kk = (kb - kb_lo) * 32; }
        uint32_t dA = sbase + buf * STAGE_B + rr * 80u + c8 * 8u;
        const __half* gA = Ab + (size_t)(row0 + rr) * ldaH + kk + c8 * 4;
#pragma unroll
        for (int i = 0; i < 4; i++)
            cp8(dA + i * 32 * 80u, gA + (size_t)i * 32 * ldaH);
        uint32_t dB = dA + 10240u;
        const __half* gB = BT + (size_t)(col0 + rr) * ldbH + kb * 32 + c8 * 4;
#pragma unroll
        for (int i = 0; i < 4; i++)
            cp8(dB + i * 32 * 80u, gB + (size_t)i * 32 * ldbH);
        asm volatile("cp.async.commit_group;" ::: "memory");
    };
    auto commit_empty = [&]() {
        asm volatile("cp.async.commit_group;" ::: "memory");
    };

    issue(0);
    if (nkb > 1) issue(1); else commit_empty();

    for (int kb = 0; kb < nkb; kb++) {
        if (kb + 2 < nkb) issue(kb + 2); else commit_empty();
        asm volatile("cp.async.wait_group 2;" ::: "memory");
        __syncthreads();
        int buf = kb & 3;
        const __half(*As)[40] = (const __half(*)[40])(dyn + buf * STAGE_H);
        const __half(*Bs)[40] = (const __half(*)[40])(dyn + buf * STAGE_H + 5120);
#pragma unroll
        for (int s = 0; s < 2; s++) {
            uint32_t af[4][4], bf[4][2];
#pragma unroll
            for (int mi = 0; mi < 4; mi++) {
                int m = wm * 64 + mi * 16 + gid;
                af[mi][0] = *(const uint32_t*)&As[m][s * 16 + 2 * tg];
                af[mi][1] = *(const uint32_t*)&As[m + 8][s * 16 + 2 * tg];
                af[mi][2] = *(const uint32_t*)&As[m][s * 16 + 2 * tg + 8];
                af[mi][3] = *(const uint32_t*)&As[m + 8][s * 16 + 2 * tg + 8];
            }
#pragma unroll
            for (int ni = 0; ni < 4; ni++) {
                int n = wn * 32 + ni * 8 + gid;
                bf[ni][0] = *(const uint32_t*)&Bs[n][s * 16 + 2 * tg];
                bf[ni][1] = *(const uint32_t*)&Bs[n][s * 16 + 2 * tg + 8];
            }
#pragma unroll
            for (int mi = 0; mi < 4; mi++)
#pragma unroll
                for (int ni = 0; ni < 4; ni++) {
                    asm volatile(
                        "mma.sync.aligned.m16n8k16.row.col.f32.f16.f16.f32 "
                        "{%0,%1,%2,%3}, {%4,%5,%6,%7}, {%8,%9}, {%0,%1,%2,%3};"
                        : "+f"(acc[mi][ni][0]), "+f"(acc[mi][ni][1]),
                          "+f"(acc[mi][ni][2]), "+f"(acc[mi][ni][3])
                        : "r"(af[mi][0]), "r"(af[mi][1]), "r"(af[mi][2]), "r"(af[mi][3]),
                          "r"(bf[ni][0]), "r"(bf[ni][1]));
                }
        }
    }

    // epilogue
#pragma unroll
    for (int mi = 0; mi < 4; mi++) {
#pragma unroll
        for (int ni = 0; ni < 4; ni++) {
#pragma unroll
            for (int q = 0; q < 4; q++) {
                int r = row0 + wm * 64 + mi * 16 + gid + (q >> 1) * 8;
                int c = col0 + wn * 32 + ni * 8 + tg * 2 + (q & 1);
                if (r >= M || c >= N) continue;
                float v = acc[mi][ni][q];
                if (bias) v += bias[c];
                if (base) v += base[(r >> 9) * base_ld + c];
                if (act == 1) v = gelu_f(v);
                else if (act == 2) v = tanhf(v);
                C[(size_t)r * ldc + c] = v;
            }
        }
    }
}

// ---------------- fp32 SGEMM (FFT transforms only) ----------------
__global__ void k_gemm(const float* __restrict__ A, int lda,
                       const float* __restrict__ B, int ldb,
                       float* __restrict__ C, int ldc,
                       int M, int N, int K) {
    __shared__ float As[8][128];
    __shared__ float Bs[8][128];
    int tid = threadIdx.x;
    int row0 = blockIdx.y * 128, col0 = blockIdx.x * 128;
    int ty = tid >> 4, tx = tid & 15;
    int ar = tid >> 1, ac = (tid & 1) * 4;
    int br = tid >> 5, bc = (tid & 31) * 4;
    float acc[8][8];
#pragma unroll
    for (int i = 0; i < 8; i++)
#pragma unroll
        for (int j = 0; j < 8; j++) acc[i][j] = 0.f;
    for (int k0 = 0; k0 < K; k0 += 8) {
        int gr = row0 + ar;
#pragma unroll
        for (int u = 0; u < 4; u++) {
            int gk = k0 + ac + u;
            As[ac + u][ar] = (gr < M && gk < K) ? A[(size_t)gr * lda + gk] : 0.f;
        }
        int gk = k0 + br;
#pragma unroll
        for (int u = 0; u < 4; u++) {
            int gc = col0 + bc + u;
            Bs[br][bc + u] = (gk < K && gc < N) ? B[(size_t)gk * ldb + gc] : 0.f;
        }
        __syncthreads();
#pragma unroll
        for (int kk = 0; kk < 8; kk++) {
            float a_[8], b_[8];
#pragma unroll
            for (int i = 0; i < 8; i++) a_[i] = As[kk][ty * 8 + i];
#pragma unroll
            for (int j = 0; j < 8; j++) b_[j] = Bs[kk][tx * 8 + j];
#pragma unroll
            for (int i = 0; i < 8; i++)
#pragma unroll
                for (int j = 0; j < 8; j++)
                    acc[i][j] = fmaf(a_[i], b_[j], acc[i][j]);
        }
        __syncthreads();
    }
#pragma unroll
    for (int i = 0; i < 8; i++) {
        int r = row0 + ty * 8 + i;
        if (r >= M) continue;
#pragma unroll
        for (int j = 0; j < 8; j++) {
            int c = col0 + tx * 8 + j;
            if (c < N) C[(size_t)r * ldc + c] = acc[i][j];
        }
    }
}

// ---------------- per-batch constant base ----------------
__global__ void k_base(const float* __restrict__ src, const float* __restrict__ tgt,
                       const float* __restrict__ w1, const float* __restrict__ b1,
                       int out_off) {
    int b = blockIdx.y;
    int tid = threadIdx.x;
    int jj = tid & 31;
    int ks = tid >> 5;
    int j = blockIdx.x * 32 + jj;
    float s = 0.f;
    if (j < F4) {
        const float* ps = src + b * 513;
        const float* pt = tgt + b * 513;
        for (int k = ks * 128; k < ks * 128 + 128; k++) {
            float x = (k < 512) ? ps[k] : pt[k - 512];
            s = fmaf(x, w1[(size_t)(F4 + k) * F4 + j], s);
        }
    }
    __shared__ float sh[8][32];
    sh[ks][jj] = s;
    __syncthreads();
    if (ks == 0 && j < F4) {
        float t = b1[j];
#pragma unroll
        for (int q = 0; q < 8; q++) t += sh[q][jj];
        g_base[b * NBASE + out_off + j] = t;
    }
}

// ---------------- rfft output -> fp16 state copy ----------------
__global__ void k_convert() {
    int r = blockIdx.x, tid = threadIdx.x;
    const float2* sc = (const float2*)(g_ct + (size_t)r * F4);
    const float2* st = (const float2*)(g_ct + (size_t)r * F4 + F2);
    __half2* dc = (__half2*)(g_ct_h + (size_t)r * KD);
    __half2* dt = (__half2*)(g_ct_h + (size_t)(ROWS + r) * KD);
    for (int j = tid; j < 257; j += 256) {
        dc[j] = __float22half2_rn(sc[j]);
        dt[j] = __float22half2_rn(st[j]);
    }
}

// ---------------- LayerNorm + exact GELU -> fp16 hidden ----------------
__global__ void k_ln_gelu(const float* __restrict__ gc, const float* __restrict__ bc,
                          const float* __restrict__ gt, const float* __restrict__ bt) {
    if (g_done) return;
    int r = blockIdx.x, h = blockIdx.y, tid = threadIdx.x;
    const float* g = h ? gt : gc;
    const float* be = h ? bt : bc;
    const float4* hr = (const float4*)(g_h + (size_t)r * 2056 + h * 1028);
    __half2* out = (__half2*)(g_h_h + (size_t)(h * ROWS + r) * KW2);
    float s = 0.f, s2 = 0.f;
    for (int j = tid; j < 257; j += 256) {
        float4 x = hr[j];
        s += x.x + x.y + x.z + x.w;
        s2 += x.x * x.x + x.y * x.y + x.z * x.z + x.w * x.w;
    }
    __shared__ float sa[256], sb[256];
    sa[tid] = s; sb[tid] = s2;
    __syncthreads();
    for (int o = 128; o > 0; o >>= 1) {
        if (tid < o) { sa[tid] += sa[tid + o]; sb[tid] += sb[tid + o]; }
        __syncthreads();
    }
    float mean = sa[0] / F4;
    float var = sb[0] / F4 - mean * mean;
    float rs = rsqrtf(var + 1e-5f);
    const float4* g4 = (const float4*)g;
    const float4* b4 = (const float4*)be;
    for (int j = tid; j < 257; j += 256) {
        float4 x = hr[j], gg = g4[j], bb = b4[j];
        float2 lo, hi;
        lo.x = gelu_f((x.x - mean) * rs * gg.x + bb.x);
        lo.y = gelu_f((x.y - mean) * rs * gg.y + bb.y);
        hi.x = gelu_f((x.z - mean) * rs * gg.z + bb.z);
        hi.y = gelu_f((x.w - mean) * rs * gg.w + bb.w);
        out[2 * j] = __float22half2_rn(lo);
        out[2 * j + 1] = __float22half2_rn(hi);
    }
}

// ---------------- fused heads + update ----------------
__global__ void k_gate_update(const float* __restrict__ fd,
                              const float* __restrict__ dw2, const float* __restrict__ db2,
                              const float* __restrict__ sw2, const float* __restrict__ sb2,
                              const float* __restrict__ cs_p, const float* __restrict__ ts_p) {
    if (g_done) return;
    int row = blockIdx.x, tid = threadIdx.x;
    const float* gc = g_g + (size_t)row * 512;
    const float* gt = g_g + (size_t)(ROWS + row) * 512;
    float s1 = 0.f, s2 = 0.f, s3 = 0.f;
    for (int k = tid; k < 257; k += 256) {
        float w = dw2[k];
        s1 = fmaf(gc[k], w, s1);
        s2 = fmaf(gt[k], w, s2);
    }
    if (tid < 128) s3 = gc[257 + tid] * sw2[tid];
    __shared__ float h1[256], h2[256], h3[256];
    h1[tid] = s1; h2[tid] = s2; h3[tid] = s3;
    __syncthreads();
    for (int o = 128; o > 0; o >>= 1) {
        if (tid < o) { h1[tid] += h1[tid + o]; h2[tid] += h2[tid + o]; h3[tid] += h3[tid + o]; }
        __syncthreads();
    }
    __shared__ float sh_ac, sh_at;
    if (tid == 0) {
        float a_c = 1.f / (1.f + expf(-(h1[0] + db2[0])));
        float a_t = 1.f / (1.f + expf(-(h2[0] + db2[0])));
        if (isnan(a_c)) a_c = 0.f;
        if (isnan(a_t)) a_t = 0.f;
        float gam = 1.f / (1.f + expf(-(h3[0] + sb2[0]))) + 0.5f;
        sh_ac = gam * a_c * (*cs_p);
        sh_at = gam * a_t * (*ts_p);
    }
    __syncthreads();
    float ac = sh_ac, at = sh_at;

    const float2* ct_c = (const float2*)(g_ct + (size_t)row * F4);
    const float2* ct_t = (const float2*)(g_ct + (size_t)row * F4 + F2);
    const float2* fc2 = (const float2*)(g_fct + (size_t)row * F2);
    const float2* ft2 = (const float2*)(g_fct + (size_t)(ROWS + row) * F2);
    float2* nw_c = (float2*)(g_new + (size_t)row * F4);
    float2* nw_t = (float2*)(g_new + (size_t)row * F4 + F2);
    float dc2 = 0.f, dt2 = 0.f, sc2 = 0.f, st2 = 0.f;
    for (int j2 = tid; j2 < 257; j2 += 256) {
        int j = 2 * j2;
        float fd0 = fd[j < NF ? j : j - NF];
        float fd1 = fd[(j + 1) < NF ? (j + 1) : (j + 1 - NF)];
        float2 c = ct_c[j2], f = fc2[j2];
        float2 nc;
        nc.x = fmaf(fd0, c.x, ac * f.x);
        nc.y = fmaf(fd1, c.y, ac * f.y);
        nw_c[j2] = nc;
        float d0 = nc.x - c.x, d1 = nc.y - c.y;
        dc2 += d0 * d0 + d1 * d1; sc2 += nc.x * nc.x + nc.y * nc.y;
        float2 t = ct_t[j2], ff = ft2[j2];
        float2 nt;
        nt.x = fmaf(fd0, t.x, at * ff.x);
        nt.y = fmaf(fd1, t.y, at * ff.y);
        nw_t[j2] = nt;
        d0 = nt.x - t.x; d1 = nt.y - t.y;
        dt2 += d0 * d0 + d1 * d1; st2 += nt.x * nt.x + nt.y * nt.y;
    }
    h1[tid] = dc2; h2[tid] = dt2; h3[tid] = sc2;
    __shared__ float h4[256];
    h4[tid] = st2;
    __syncthreads();
    for (int o = 128; o > 0; o >>= 1) {
        if (tid < o) { h1[tid] += h1[tid + o]; h2[tid] += h2[tid + o];
                       h3[tid] += h3[tid + o]; h4[tid] += h4[tid + o]; }
        __syncthreads();
    }
    if (tid == 0) {
        g_rn_c[row] = sqrtf(h1[0]);
        g_rn_t[row] = sqrtf(h2[0]);
        g_sq_c[row] = h3[0];
        g_sq_t[row] = h4[0];
    }
}

// ---------------- reduce + convergence decision ----------------
__global__ void k_reduce_finalize() {
    __shared__ float4 sh[1024];
    int tid = threadIdx.x;
    float4 a = make_float4(0.f, 0.f, 0.f, 0.f);
    for (int i = tid; i < ROWS; i += 1024) {
        a.x += g_rn_c[i]; a.y += g_rn_t[i]; a.z += g_sq_c[i]; a.w += g_sq_t[i];
    }
    sh[tid] = a;
    __syncthreads();
    for (int o = 512; o > 0; o >>= 1) {
        if (tid < o) {
            sh[tid].x += sh[tid + o].x; sh[tid].y += sh[tid + o].y;
            sh[tid].z += sh[tid + o].z; sh[tid].w += sh[tid + o].w;
        }
        __syncthreads();
    }
    if (tid == 0) {
        if (g_done) {
            g_scal[2] = 0.f;
        } else {
            float dc = sh[0].x / (float)ROWS;
            float dt = sh[0].y / (float)ROWS;
            float nc = sqrtf(sh[0].z);
            float nt = sqrtf(sh[0].w);
            int conv = (dc < TOLV) && (dt < TOLV);
            g_scal[0] = conv ? 1.f : (nc > 10.f ? 10.f / nc : 1.f);
            g_scal[1] = conv ? 1.f : (nt > 10.f ? 10.f / nt : 1.f);
            g_scal[2] = 1.f;
            if (conv) g_done = 1;
        }
    }
}

// ---------------- apply: commit state (fp32 + fp16) ----------------
__global__ void k_apply() {
    if (g_scal[2] == 0.f) return;
    int r = blockIdx.x, tid = threadIdx.x;
    float sc = g_scal[0], st = g_scal[1];
    const float2* nw = (const float2*)(g_new + (size_t)r * F4);
    float2* ct = (float2*)(g_ct + (size_t)r * F4);
    __half2* hc = (__half2*)(g_ct_h + (size_t)r * KD);
    __half2* ht = (__half2*)(g_ct_h + (size_t)(ROWS + r) * KD);
    for (int j = tid; j < 257; j += 256) {
        float2 v = nw[j];
        v.x *= sc; v.y *= sc;
        ct[j] = v;
        hc[j] = __float22half2_rn(v);
        float2 w = nw[257 + j];
        w.x *= st; w.y *= st;
        ct[257 + j] = w;
        ht[j] = __float22half2_rn(w);
    }
}

// ---------------- host launch ----------------
extern "C" void kernel_launch(void* const* d_in, const int* in_sizes, int n_in,
                              void* d_out, int out_size) {
    const float* carrier = (const float*)d_in[0];
    const float* traj    = (const float*)d_in[1];
    const float* srcp    = (const float*)d_in[2];
    const float* tgtp    = (const float*)d_in[3];
    const float* cw1 = (const float*)d_in[4];
    const float* cb1 = (const float*)d_in[5];
    const float* cg  = (const float*)d_in[6];
    const float* cbe = (const float*)d_in[7];
    const float* cw2 = (const float*)d_in[8];
    const float* cb2 = (const float*)d_in[9];
    const float* tw1 = (const float*)d_in[10];
    const float* tb1 = (const float*)d_in[11];
    const float* tg_ = (const float*)d_in[12];
    const float* tbe = (const float*)d_in[13];
    const float* tw2 = (const float*)d_in[14];
    const float* tb2 = (const float*)d_in[15];
    const float* fd  = (const float*)d_in[16];
    const float* dw1 = (const float*)d_in[17];
    const float* db1 = (const float*)d_in[18];
    const float* dw2 = (const float*)d_in[19];
    const float* db2 = (const float*)d_in[20];
    const float* sw1 = (const float*)d_in[21];
    const float* sb1 = (const float*)d_in[22];
    const float* sw2 = (const float*)d_in[23];
    const float* sb2 = (const float*)d_in[24];
    const float* csc = (const float*)d_in[25];
    const float* tsc = (const float*)d_in[26];
    float* out = (float*)d_out;

    float *p_ct, *p_h, *p_fct, *p_g, *p_Br, *p_Bi, *p_base, *p_gbias;
    __half *p_ct_h, *p_h_h, *p_w1T, *p_cw2T, *p_tw2T, *p_gwT;
    cudaGetSymbolAddress((void**)&p_ct,   g_ct);
    cudaGetSymbolAddress((void**)&p_h,    g_h);
    cudaGetSymbolAddress((void**)&p_fct,  g_fct);
    cudaGetSymbolAddress((void**)&p_g,    g_g);
    cudaGetSymbolAddress((void**)&p_Br,   g_Br);
    cudaGetSymbolAddress((void**)&p_Bi,   g_Bi);
    cudaGetSymbolAddress((void**)&p_base, g_base);
    cudaGetSymbolAddress((void**)&p_gbias,g_gbias);
    cudaGetSymbolAddress((void**)&p_ct_h, g_ct_h);
    cudaGetSymbolAddress((void**)&p_h_h,  g_h_h);
    cudaGetSymbolAddress((void**)&p_w1T,  g_w1T);
    cudaGetSymbolAddress((void**)&p_cw2T, g_cw2T);
    cudaGetSymbolAddress((void**)&p_tw2T, g_tw2T);
    cudaGetSymbolAddress((void**)&p_gwT,  g_gwT);

    static int s_attr_done = 0;
    if (!s_attr_done) {
        cudaFuncSetAttribute(k_gemm_h, cudaFuncAttributeMaxDynamicSharedMemorySize,
                             SMEM_BYTES);
        s_attr_done = 1;
    }

    dim3 th(256);
    auto grid = [](int N, int M) { return dim3((N + 127) / 128, (M + 127) / 128); };

    // 0) tables + done reset
    k_init_tables<<<(SPATIAL * NF + 255) / 256, 256>>>();

    // 0b) weight transposes (pads stay zero)
    k_tr<<<dim3(3, 1028), th>>>(cw1, 514, F4, p_w1T, KW1, 0);
    k_tr<<<dim3(3, 1028), th>>>(cw1 + (size_t)514 * F4, 514, F4, p_w1T + 544, KW1, 0);
    k_tr<<<dim3(3, 1028), th>>>(tw1, 514, F4, p_w1T, KW1, 1028);
    k_tr<<<dim3(3, 1028), th>>>(tw1 + (size_t)514 * F4, 514, F4, p_w1T + 544, KW1, 1028);
    k_tr<<<dim3(5, 514), th>>>(cw2, F4, F2, p_cw2T, KW2, 0);
    k_tr<<<dim3(5, 514), th>>>(tw2, F4, F2, p_tw2T, KW2, 0);
    k_tr<<<dim3(3, 257), th>>>(dw1, F2, NF, p_gwT, KD, 0);
    k_tr<<<dim3(3, 128), th>>>(sw1, F2, FH, p_gwT, KD, 257);
    k_gbias<<<2, th>>>(db1, sb1);

    // 1) rfft as fp32 DFT-GEMM, then fp16 state copy
    k_gemm<<<grid(F2, ROWS), th>>>(carrier, SPATIAL, p_Br, F2, p_ct, F4, ROWS, F2, SPATIAL);
    k_gemm<<<grid(F2, ROWS), th>>>(traj, SPATIAL, p_Br, F2, p_ct + F2, F4, ROWS, F2, SPATIAL);
    k_convert<<<ROWS, th>>>();

    // 2) per-batch constant base
    dim3 bg((F4 + 31) / 32, BSZ);
    k_base<<<bg, th>>>(srcp, tgtp, cw1, cb1, 0);
    k_base<<<bg, th>>>(srcp, tgtp, tw1, tb1, 1028);

    // 3) 20 fixed-point steps
    for (int s = 0; s < MAX_STEPS; s++) {
        // merged freq-net GEMM1: [4096 x 2056]
        k_gemm_h<<<grid(2056, ROWS), th, SMEM_BYTES>>>(
            p_ct_h, p_ct_h + (size_t)ROWS * KD, KD, 17,
            p_w1T, p_w1T, KW1, ROWS,
            p_h, 2056, ROWS, 2056, KW1 / 32,
            nullptr, nullptr, p_base, NBASE, 0, 1);
        // LN + GELU -> fp16 hidden
        k_ln_gelu<<<dim3(ROWS, 2), th>>>(cg, cbe, tg_, tbe);
        // merged GEMM2: [8192 x 514]
        k_gemm_h<<<grid(F2, 2 * ROWS), th, SMEM_BYTES>>>(
            p_h_h, p_h_h, KW2, KW2 / 32,
            p_cw2T, p_tw2T, KW2, ROWS,
            p_fct, F2, 2 * ROWS, F2, KW2 / 32,
            cb2, tb2, nullptr, 0, 2, 1);
        // merged gating GEMM: [8192 x 385] (hd | hs)
        k_gemm_h<<<grid(NG, 2 * ROWS), th, SMEM_BYTES>>>(
            p_ct_h, p_ct_h, KD, KD / 32,
            p_gwT, p_gwT, KD, 2 * ROWS,
            p_g, 512, 2 * ROWS, NG, KD / 32,
            p_gbias, p_gbias, nullptr, 0, 1, 1);
        // heads + update fused
        k_gate_update<<<ROWS, th>>>(fd, dw2, db2, sw2, sb2, csc, tsc);
        k_reduce_finalize<<<1, 1024>>>();
        k_apply<<<ROWS, th>>>();
    }

    // 4) irfft as fp32 DFT-GEMM
    k_gemm<<<grid(SPATIAL, ROWS), th>>>(p_ct, F4, p_Bi, SPATIAL, out, SPATIAL,
                                        ROWS, SPATIAL, F2);
    k_gemm<<<grid(SPATIAL, ROWS), th>>>(p_ct + F2, F4, p_Bi, SPATIAL,
                                        out + (size_t)ROWS * SPATIAL, SPATIAL,
                                        ROWS, SPATIAL, F2);
    (void)in_sizes; (void)n_in; (void)out_size;
}

// round 9
// speedup vs baseline: 6.5738x; 1.0615x over previous
#include <cuda_runtime.h>
#include <cuda_fp16.h>
#include <math.h>
#include <stdint.h>

// ---------------- problem constants ----------------
#define BSZ 8
#define SEQ 512
#define ROWS 4096          // BSZ*SEQ
#define SPATIAL 512
#define NF 257             // rfft bins
#define F2 514
#define F4 1028
#define FH 128
#define MAX_STEPS 20
#define TOLV 1e-3f
// padded GEMM dims
#define KW1 1088           // GEMM1 K: 2*544
#define NW1 2176
#define KW2 1056           // GEMM2 K
#define NW2 640
#define KD  544            // gating K / fp16 state row
#define NG  385            // gating N: 257 hd + 128 hs
#define NGP 512
#define NBASE 2176
// FFT split-fp16 GEMM dims
#define KFR 1536           // rfft K: 3*512
#define KFI 1632           // irfft K: 3*544
// GEMM smem: 4 stages x (A 128x40 + B 128x40) halfs
#define STAGE_H 10240
#define STAGE_B 20480
#define SMEM_BYTES (4 * STAGE_B)

// ---------------- device scratch (static, zero-initialized) ----------------
__device__ float g_ct[2 * ROWS * F2];      // fp32 state: rows 0..4095 c, 4096.. t
__device__ float g_new[2 * ROWS * F2];
__device__ float g_h[ROWS * 2056];         // merged GEMM1 output
__device__ float g_fct[2 * ROWS * F2];     // rows 0..4095 fc, 4096.. ft
__device__ float g_g[2 * ROWS * 512];      // gating hidden: cols 0..256 hd, 257..384 hs
__device__ float g_base[BSZ * NBASE];
__device__ float g_gbias[NGP];
__device__ float g_rn_c[ROWS], g_rn_t[ROWS], g_sq_c[ROWS], g_sq_t[ROWS];
__device__ float g_scal[4];
__device__ int   g_done;
// fp16 activations (pads never written -> stay zero)
__device__ __half g_ct_h[2 * ROWS * KD];
__device__ __half g_h_h[2 * ROWS * KW2];
// fp16 K-major weights (pads stay zero)
__device__ __half g_w1T[NW1 * KW1];
__device__ __half g_cw2T[NW2 * KW2];
__device__ __half g_tw2T[NW2 * KW2];
__device__ __half g_gwT[NGP * KD];
// split-fp16 FFT operands/tables
__device__ __half g_fftA[2 * ROWS * KFR];  // [x_hi | x_hi | x_lo]
__device__ __half g_irA[2 * ROWS * KFI];   // [s_hi | s_hi | s_lo]
__device__ __half g_BrT[640 * KFR];        // rfft BT rows: [B_hi | B_lo | B_hi]
__device__ __half g_BiT[512 * KFI];        // irfft BT rows: [B_hi | B_lo | B_hi]

// ---------------- helpers ----------------
__device__ __forceinline__ float gelu_f(float x) {
    return 0.5f * x * (1.0f + erff(x * 0.70710678118654752f));
}
__device__ __forceinline__ uint32_t smem_u32(const void* p) {
    uint32_t a;
    asm("{ .reg .u64 t; cvta.to.shared.u64 t, %1; cvt.u32.u64 %0, t; }" : "=r"(a) : "l"(p));
    return a;
}
__device__ __forceinline__ void cp8(uint32_t dst, const void* src) {
    asm volatile("cp.async.ca.shared.global [%0], [%1], 8;" :: "r"(dst), "l"(src));
}

// ---------------- table init: split-fp16 DFT tables ----------------
__global__ void k_init_tables() {
    int idx = blockIdx.x * blockDim.x + threadIdx.x;
    if (idx == 0) g_done = 0;
    int total = SPATIAL * NF;
    if (idx >= total) return;
    int n = idx / NF, q = idx % NF;
    double r = (double)((q * n) & 511) / 256.0;
    double sv, cv;
    sincospi(r, &sv, &cv);
    // rfft rows j=2q (cos), j=2q+1 (-sin); col layout [hi(512) | lo(512) | hi(512)]
    float cf = (float)cv, sf = (float)(-sv);
    __half chh = __float2half_rn(cf), shh = __float2half_rn(sf);
    __half cll = __float2half_rn(cf - __half2float(chh));
    __half sll = __float2half_rn(sf - __half2float(shh));
    __half* Rc = g_BrT + (size_t)(2 * q) * KFR;
    __half* Rs = g_BrT + (size_t)(2 * q + 1) * KFR;
    Rc[n] = chh; Rc[512 + n] = cll; Rc[1024 + n] = chh;
    Rs[n] = shh; Rs[512 + n] = sll; Rs[1024 + n] = shh;
    // irfft row n; col layout [hi(544) | lo(544) | hi(544)]
    double w = (q == 0 || q == NF - 1) ? 1.0 : 2.0;
    float ic = (float)(w * cv / 512.0), is = (float)(-w * sv / 512.0);
    __half ich = __float2half_rn(ic), ish = __float2half_rn(is);
    __half icl = __float2half_rn(ic - __half2float(ich));
    __half isl = __float2half_rn(is - __half2float(ish));
    __half* Bn = g_BiT + (size_t)n * KFI;
    Bn[2 * q] = ich;        Bn[544 + 2 * q] = icl;        Bn[1088 + 2 * q] = ich;
    Bn[2 * q + 1] = ish;    Bn[544 + 2 * q + 1] = isl;    Bn[1088 + 2 * q + 1] = ish;
}

// ---------------- input split: carrier/traj -> [hi|hi|lo] fp16 ----------------
__global__ void k_split_in(const float* __restrict__ carrier, const float* __restrict__ traj) {
    int r = blockIdx.x, tid = threadIdx.x;
    const float* src = (r < ROWS) ? carrier + (size_t)r * SPATIAL
                                  : traj + (size_t)(r - ROWS) * SPATIAL;
    __half* d = g_fftA + (size_t)r * KFR;
    for (int k = tid; k < SPATIAL; k += 256) {
        float x = src[k];
        __half h = __float2half_rn(x);
        __half l = __float2half_rn(x - __half2float(h));
        d[k] = h; d[512 + k] = h; d[1024 + k] = l;
    }
}

// ---------------- state split for irfft ----------------
__global__ void k_split_state() {
    int r = blockIdx.x, tid = threadIdx.x;
    const float* src = g_ct + (size_t)r * F2;
    __half* d = g_irA + (size_t)r * KFI;
    for (int j = tid; j < F2; j += 256) {
        float x = src[j];
        __half h = __float2half_rn(x);
        __half l = __float2half_rn(x - __half2float(h));
        d[j] = h; d[544 + j] = h; d[1088 + j] = l;
    }
}

// ---------------- transpose W[k][n] -> WT[(n_off+n)*ldk + k] fp16 ----------------
__global__ void k_tr(const float* __restrict__ W, int K, int N,
                     __half* __restrict__ WT, int ldk, int n_off) {
    int k = blockIdx.x * 256 + threadIdx.x;
    int n = blockIdx.y;
    if (k >= K) return;
    WT[(size_t)(n_off + n) * ldk + k] = __float2half_rn(W[(size_t)k * N + n]);
}

// ---------------- gating bias concat ----------------
__global__ void k_gbias(const float* __restrict__ db1, const float* __restrict__ sb1) {
    int i = threadIdx.x + blockIdx.x * 256;
    if (i >= NGP) return;
    g_gbias[i] = (i < 257) ? db1[i] : (i < NG ? sb1[i - 257] : 0.f);
}

// =====================================================================
// FP16 tensor GEMM, 4-stage cp.async pipeline, one sync per K-block,
// 2 CTAs/SM. C = act(A @ BT^T + bias + base); optional fp16 copy Ch.
// =====================================================================
__global__ __launch_bounds__(256, 2) void k_gemm_h(
    const __half* __restrict__ A_lo, const __half* __restrict__ A_hi,
    int ldaH, int kb_lo,
    const __half* __restrict__ B_lo, const __half* __restrict__ B_hi,
    int ldbH, int M_lo,
    float* __restrict__ C, int ldc, int M, int N, int nkb,
    const float* __restrict__ bias_lo, const float* __restrict__ bias_hi,
    const float* __restrict__ base, int base_ld,
    __half* __restrict__ Ch, int ldch,
    int act, int chk) {
    if (chk && g_done) return;
    extern __shared__ __half dyn[];

    const int tid = threadIdx.x;
    const int warp = tid >> 5, lane = tid & 31;
    const int gid = lane >> 2, tg = lane & 3;
    const int wm = warp & 1, wn = warp >> 1;
    const int row0 = blockIdx.y * 128, col0 = blockIdx.x * 128;

    const __half* BT = (row0 < M_lo) ? B_lo : B_hi;
    const float* bias = (row0 < M_lo) ? bias_lo : bias_hi;

    float acc[4][4][4];
#pragma unroll
    for (int mi = 0; mi < 4; mi++)
#pragma unroll
        for (int ni = 0; ni < 4; ni++)
#pragma unroll
            for (int q = 0; q < 4; q++) acc[mi][ni][q] = 0.f;

    const uint32_t sbase = smem_u32(dyn);
    const int rr = tid >> 3;
    const int c8 = tid & 7;

    auto issue = [&](int kb) {
        int buf = kb & 3;
        const __half* Ab;
        int kk;
        if (kb < kb_lo) { Ab = A_lo; kk = kb * 32; }
        else            { Ab = A_hi; kk = (kb - kb_lo) * 32; }
        uint32_t dA = sbase + buf * STAGE_B + rr * 80u + c8 * 8u;
        const __half* gA = Ab + (size_t)(row0 + rr) * ldaH + kk + c8 * 4;
#pragma unroll
        for (int i = 0; i < 4; i++)
            cp8(dA + i * 32 * 80u, gA + (size_t)i * 32 * ldaH);
        uint32_t dB = dA + 10240u;
        const __half* gB = BT + (size_t)(col0 + rr) * ldbH + kb * 32 + c8 * 4;
#pragma unroll
        for (int i = 0; i < 4; i++)
            cp8(dB + i * 32 * 80u, gB + (size_t)i * 32 * ldbH);
        asm volatile("cp.async.commit_group;" ::: "memory");
    };
    auto commit_empty = [&]() {
        asm volatile("cp.async.commit_group;" ::: "memory");
    };

    issue(0);
    if (nkb > 1) issue(1); else commit_empty();

    for (int kb = 0; kb < nkb; kb++) {
        if (kb + 2 < nkb) issue(kb + 2); else commit_empty();
        asm volatile("cp.async.wait_group 2;" ::: "memory");
        __syncthreads();
        int buf = kb & 3;
        const __half(*As)[40] = (const __half(*)[40])(dyn + buf * STAGE_H);
        const __half(*Bs)[40] = (const __half(*)[40])(dyn + buf * STAGE_H + 5120);
#pragma unroll
        for (int s = 0; s < 2; s++) {
            uint32_t af[4][4], bf[4][2];
#pragma unroll
            for (int mi = 0; mi < 4; mi++) {
                int m = wm * 64 + mi * 16 + gid;
                af[mi][0] = *(const uint32_t*)&As[m][s * 16 + 2 * tg];
                af[mi][1] = *(const uint32_t*)&As[m + 8][s * 16 + 2 * tg];
                af[mi][2] = *(const uint32_t*)&As[m][s * 16 + 2 * tg + 8];
                af[mi][3] = *(const uint32_t*)&As[m + 8][s * 16 + 2 * tg + 8];
            }
#pragma unroll
            for (int ni = 0; ni < 4; ni++) {
                int n = wn * 32 + ni * 8 + gid;
                bf[ni][0] = *(const uint32_t*)&Bs[n][s * 16 + 2 * tg];
                bf[ni][1] = *(const uint32_t*)&Bs[n][s * 16 + 2 * tg + 8];
            }
#pragma unroll
            for (int mi = 0; mi < 4; mi++)
#pragma unroll
                for (int ni = 0; ni < 4; ni++) {
                    asm volatile(
                        "mma.sync.aligned.m16n8k16.row.col.f32.f16.f16.f32 "
                        "{%0,%1,%2,%3}, {%4,%5,%6,%7}, {%8,%9}, {%0,%1,%2,%3};"
                        : "+f"(acc[mi][ni][0]), "+f"(acc[mi][ni][1]),
                          "+f"(acc[mi][ni][2]), "+f"(acc[mi][ni][3])
                        : "r"(af[mi][0]), "r"(af[mi][1]), "r"(af[mi][2]), "r"(af[mi][3]),
                          "r"(bf[ni][0]), "r"(bf[ni][1]));
                }
        }
    }

    // epilogue
#pragma unroll
    for (int mi = 0; mi < 4; mi++) {
#pragma unroll
        for (int ni = 0; ni < 4; ni++) {
#pragma unroll
            for (int q = 0; q < 4; q++) {
                int r = row0 + wm * 64 + mi * 16 + gid + (q >> 1) * 8;
                int c = col0 + wn * 32 + ni * 8 + tg * 2 + (q & 1);
                if (r >= M || c >= N) continue;
                float v = acc[mi][ni][q];
                if (bias) v += bias[c];
                if (base) v += base[(r >> 9) * base_ld + c];
                if (act == 1) v = gelu_f(v);
                else if (act == 2) v = tanhf(v);
                C[(size_t)r * ldc + c] = v;
                if (Ch) Ch[(size_t)r * ldch + c] = __float2half_rn(v);
            }
        }
    }
}

// ---------------- per-batch constant base ----------------
__global__ void k_base(const float* __restrict__ src, const float* __restrict__ tgt,
                       const float* __restrict__ w1, const float* __restrict__ b1,
                       int out_off) {
    int b = blockIdx.y;
    int tid = threadIdx.x;
    int jj = tid & 31;
    int ks = tid >> 5;
    int j = blockIdx.x * 32 + jj;
    float s = 0.f;
    if (j < F4) {
        const float* ps = src + b * 513;
        const float* pt = tgt + b * 513;
        for (int k = ks * 128; k < ks * 128 + 128; k++) {
            float x = (k < 512) ? ps[k] : pt[k - 512];
            s = fmaf(x, w1[(size_t)(F4 + k) * F4 + j], s);
        }
    }
    __shared__ float sh[8][32];
    sh[ks][jj] = s;
    __syncthreads();
    if (ks == 0 && j < F4) {
        float t = b1[j];
#pragma unroll
        for (int q = 0; q < 8; q++) t += sh[q][jj];
        g_base[b * NBASE + out_off + j] = t;
    }
}

// ---------------- LayerNorm + exact GELU -> fp16 hidden ----------------
__global__ void k_ln_gelu(const float* __restrict__ gc, const float* __restrict__ bc,
                          const float* __restrict__ gt, const float* __restrict__ bt) {
    if (g_done) return;
    int r = blockIdx.x, h = blockIdx.y, tid = threadIdx.x;
    const float* g = h ? gt : gc;
    const float* be = h ? bt : bc;
    const float4* hr = (const float4*)(g_h + (size_t)r * 2056 + h * 1028);
    __half2* out = (__half2*)(g_h_h + (size_t)(h * ROWS + r) * KW2);
    float s = 0.f, s2 = 0.f;
    for (int j = tid; j < 257; j += 256) {
        float4 x = hr[j];
        s += x.x + x.y + x.z + x.w;
        s2 += x.x * x.x + x.y * x.y + x.z * x.z + x.w * x.w;
    }
    __shared__ float sa[256], sb[256];
    sa[tid] = s; sb[tid] = s2;
    __syncthreads();
    for (int o = 128; o > 0; o >>= 1) {
        if (tid < o) { sa[tid] += sa[tid + o]; sb[tid] += sb[tid + o]; }
        __syncthreads();
    }
    float mean = sa[0] / F4;
    float var = sb[0] / F4 - mean * mean;
    float rs = rsqrtf(var + 1e-5f);
    const float4* g4 = (const float4*)g;
    const float4* b4 = (const float4*)be;
    for (int j = tid; j < 257; j += 256) {
        float4 x = hr[j], gg = g4[j], bb = b4[j];
        float2 lo, hi;
        lo.x = gelu_f((x.x - mean) * rs * gg.x + bb.x);
        lo.y = gelu_f((x.y - mean) * rs * gg.y + bb.y);
        hi.x = gelu_f((x.z - mean) * rs * gg.z + bb.z);
        hi.y = gelu_f((x.w - mean) * rs * gg.w + bb.w);
        out[2 * j] = __float22half2_rn(lo);
        out[2 * j + 1] = __float22half2_rn(hi);
    }
}

// ---------------- fused heads + update ----------------
__global__ void k_gate_update(const float* __restrict__ fd,
                              const float* __restrict__ dw2, const float* __restrict__ db2,
                              const float* __restrict__ sw2, const float* __restrict__ sb2,
                              const float* __restrict__ cs_p, const float* __restrict__ ts_p) {
    if (g_done) return;
    int row = blockIdx.x, tid = threadIdx.x;
    const float* gc = g_g + (size_t)row * 512;
    const float* gt = g_g + (size_t)(ROWS + row) * 512;
    float s1 = 0.f, s2 = 0.f, s3 = 0.f;
    for (int k = tid; k < 257; k += 256) {
        float w = dw2[k];
        s1 = fmaf(gc[k], w, s1);
        s2 = fmaf(gt[k], w, s2);
    }
    if (tid < 128) s3 = gc[257 + tid] * sw2[tid];
    __shared__ float h1[256], h2[256], h3[256];
    h1[tid] = s1; h2[tid] = s2; h3[tid] = s3;
    __syncthreads();
    for (int o = 128; o > 0; o >>= 1) {
        if (tid < o) { h1[tid] += h1[tid + o]; h2[tid] += h2[tid + o]; h3[tid] += h3[tid + o]; }
        __syncthreads();
    }
    __shared__ float sh_ac, sh_at;
    if (tid == 0) {
        float a_c = 1.f / (1.f + expf(-(h1[0] + db2[0])));
        float a_t = 1.f / (1.f + expf(-(h2[0] + db2[0])));
        if (isnan(a_c)) a_c = 0.f;
        if (isnan(a_t)) a_t = 0.f;
        float gam = 1.f / (1.f + expf(-(h3[0] + sb2[0]))) + 0.5f;
        sh_ac = gam * a_c * (*cs_p);
        sh_at = gam * a_t * (*ts_p);
    }
    __syncthreads();
    float ac = sh_ac, at = sh_at;

    const float2* ct_c = (const float2*)(g_ct + (size_t)row * F2);
    const float2* ct_t = (const float2*)(g_ct + (size_t)(ROWS + row) * F2);
    const float2* fc2 = (const float2*)(g_fct + (size_t)row * F2);
    const float2* ft2 = (const float2*)(g_fct + (size_t)(ROWS + row) * F2);
    float2* nw_c = (float2*)(g_new + (size_t)row * F2);
    float2* nw_t = (float2*)(g_new + (size_t)(ROWS + row) * F2);
    float dc2 = 0.f, dt2 = 0.f, sc2 = 0.f, st2 = 0.f;
    for (int j2 = tid; j2 < 257; j2 += 256) {
        int j = 2 * j2;
        float fd0 = fd[j < NF ? j : j - NF];
        float fd1 = fd[(j + 1) < NF ? (j + 1) : (j + 1 - NF)];
        float2 c = ct_c[j2], f = fc2[j2];
        float2 nc;
        nc.x = fmaf(fd0, c.x, ac * f.x);
        nc.y = fmaf(fd1, c.y, ac * f.y);
        nw_c[j2] = nc;
        float d0 = nc.x - c.x, d1 = nc.y - c.y;
        dc2 += d0 * d0 + d1 * d1; sc2 += nc.x * nc.x + nc.y * nc.y;
        float2 t = ct_t[j2], ff = ft2[j2];
        float2 nt;
        nt.x = fmaf(fd0, t.x, at * ff.x);
        nt.y = fmaf(fd1, t.y, at * ff.y);
        nw_t[j2] = nt;
        d0 = nt.x - t.x; d1 = nt.y - t.y;
        dt2 += d0 * d0 + d1 * d1; st2 += nt.x * nt.x + nt.y * nt.y;
    }
    h1[tid] = dc2; h2[tid] = dt2; h3[tid] = sc2;
    __shared__ float h4[256];
    h4[tid] = st2;
    __syncthreads();
    for (int o = 128; o > 0; o >>= 1) {
        if (tid < o) { h1[tid] += h1[tid + o]; h2[tid] += h2[tid + o];
                       h3[tid] += h3[tid + o]; h4[tid] += h4[tid + o]; }
        __syncthreads();
    }
    if (tid == 0) {
        g_rn_c[row] = sqrtf(h1[0]);
        g_rn_t[row] = sqrtf(h2[0]);
        g_sq_c[row] = h3[0];
        g_sq_t[row] = h4[0];
    }
}

// ---------------- reduce + convergence decision ----------------
__global__ void k_reduce_finalize() {
    __shared__ float4 sh[1024];
    int tid = threadIdx.x;
    float4 a = make_float4(0.f, 0.f, 0.f, 0.f);
    for (int i = tid; i < ROWS; i += 1024) {
        a.x += g_rn_c[i]; a.y += g_rn_t[i]; a.z += g_sq_c[i]; a.w += g_sq_t[i];
    }
    sh[tid] = a;
    __syncthreads();
    for (int o = 512; o > 0; o >>= 1) {
        if (tid < o) {
            sh[tid].x += sh[tid + o].x; sh[tid].y += sh[tid + o].y;
            sh[tid].z += sh[tid + o].z; sh[tid].w += sh[tid + o].w;
        }
        __syncthreads();
    }
    if (tid == 0) {
        if (g_done) {
            g_scal[2] = 0.f;
        } else {
            float dc = sh[0].x / (float)ROWS;
            float dt = sh[0].y / (float)ROWS;
            float nc = sqrtf(sh[0].z);
            float nt = sqrtf(sh[0].w);
            int conv = (dc < TOLV) && (dt < TOLV);
            g_scal[0] = conv ? 1.f : (nc > 10.f ? 10.f / nc : 1.f);
            g_scal[1] = conv ? 1.f : (nt > 10.f ? 10.f / nt : 1.f);
            g_scal[2] = 1.f;
            if (conv) g_done = 1;
        }
    }
}

// ---------------- apply: commit state (fp32 + fp16) ----------------
__global__ void k_apply() {
    if (g_scal[2] == 0.f) return;
    int r = blockIdx.x, tid = threadIdx.x;
    float sc = (r < ROWS) ? g_scal[0] : g_scal[1];
    const float2* nw = (const float2*)(g_new + (size_t)r * F2);
    float2* ct = (float2*)(g_ct + (size_t)r * F2);
    __half2* hh = (__half2*)(g_ct_h + (size_t)r * KD);
    for (int j = tid; j < 257; j += 256) {
        float2 v = nw[j];
        v.x *= sc; v.y *= sc;
        ct[j] = v;
        hh[j] = __float22half2_rn(v);
    }
}

// ---------------- host launch ----------------
extern "C" void kernel_launch(void* const* d_in, const int* in_sizes, int n_in,
                              void* d_out, int out_size) {
    const float* carrier = (const float*)d_in[0];
    const float* traj    = (const float*)d_in[1];
    const float* srcp    = (const float*)d_in[2];
    const float* tgtp    = (const float*)d_in[3];
    const float* cw1 = (const float*)d_in[4];
    const float* cb1 = (const float*)d_in[5];
    const float* cg  = (const float*)d_in[6];
    const float* cbe = (const float*)d_in[7];
    const float* cw2 = (const float*)d_in[8];
    const float* cb2 = (const float*)d_in[9];
    const float* tw1 = (const float*)d_in[10];
    const float* tb1 = (const float*)d_in[11];
    const float* tg_ = (const float*)d_in[12];
    const float* tbe = (const float*)d_in[13];
    const float* tw2 = (const float*)d_in[14];
    const float* tb2 = (const float*)d_in[15];
    const float* fd  = (const float*)d_in[16];
    const float* dw1 = (const float*)d_in[17];
    const float* db1 = (const float*)d_in[18];
    const float* dw2 = (const float*)d_in[19];
    const float* db2 = (const float*)d_in[20];
    const float* sw1 = (const float*)d_in[21];
    const float* sb1 = (const float*)d_in[22];
    const float* sw2 = (const float*)d_in[23];
    const float* sb2 = (const float*)d_in[24];
    const float* csc = (const float*)d_in[25];
    const float* tsc = (const float*)d_in[26];
    float* out = (float*)d_out;

    float *p_ct, *p_h, *p_fct, *p_g, *p_base, *p_gbias;
    __half *p_ct_h, *p_h_h, *p_w1T, *p_cw2T, *p_tw2T, *p_gwT;
    __half *p_fftA, *p_irA, *p_BrT, *p_BiT;
    cudaGetSymbolAddress((void**)&p_ct,   g_ct);
    cudaGetSymbolAddress((void**)&p_h,    g_h);
    cudaGetSymbolAddress((void**)&p_fct,  g_fct);
    cudaGetSymbolAddress((void**)&p_g,    g_g);
    cudaGetSymbolAddress((void**)&p_base, g_base);
    cudaGetSymbolAddress((void**)&p_gbias,g_gbias);
    cudaGetSymbolAddress((void**)&p_ct_h, g_ct_h);
    cudaGetSymbolAddress((void**)&p_h_h,  g_h_h);
    cudaGetSymbolAddress((void**)&p_w1T,  g_w1T);
    cudaGetSymbolAddress((void**)&p_cw2T, g_cw2T);
    cudaGetSymbolAddress((void**)&p_tw2T, g_tw2T);
    cudaGetSymbolAddress((void**)&p_gwT,  g_gwT);
    cudaGetSymbolAddress((void**)&p_fftA, g_fftA);
    cudaGetSymbolAddress((void**)&p_irA,  g_irA);
    cudaGetSymbolAddress((void**)&p_BrT,  g_BrT);
    cudaGetSymbolAddress((void**)&p_BiT,  g_BiT);

    static int s_attr_done = 0;
    if (!s_attr_done) {
        cudaFuncSetAttribute(k_gemm_h, cudaFuncAttributeMaxDynamicSharedMemorySize,
                             SMEM_BYTES);
        s_attr_done = 1;
    }

    dim3 th(256);
    auto grid = [](int N, int M) { return dim3((N + 127) / 128, (M + 127) / 128); };

    // 0) tables + done reset
    k_init_tables<<<(SPATIAL * NF + 255) / 256, 256>>>();

    // 0b) weight transposes (pads stay zero)
    k_tr<<<dim3(3, 1028), th>>>(cw1, 514, F4, p_w1T, KW1, 0);
    k_tr<<<dim3(3, 1028), th>>>(cw1 + (size_t)514 * F4, 514, F4, p_w1T + 544, KW1, 0);
    k_tr<<<dim3(3, 1028), th>>>(tw1, 514, F4, p_w1T, KW1, 1028);
    k_tr<<<dim3(3, 1028), th>>>(tw1 + (size_t)514 * F4, 514, F4, p_w1T + 544, KW1, 1028);
    k_tr<<<dim3(5, 514), th>>>(cw2, F4, F2, p_cw2T, KW2, 0);
    k_tr<<<dim3(5, 514), th>>>(tw2, F4, F2, p_tw2T, KW2, 0);
    k_tr<<<dim3(3, 257), th>>>(dw1, F2, NF, p_gwT, KD, 0);
    k_tr<<<dim3(3, 128), th>>>(sw1, F2, FH, p_gwT, KD, 257);
    k_gbias<<<2, th>>>(db1, sb1);

    // 1) rfft: split inputs, one merged split-fp16 GEMM [8192 x 514 x 1536]
    //    epilogue also writes the fp16 state copy
    k_split_in<<<2 * ROWS, th>>>(carrier, traj);
    k_gemm_h<<<grid(F2, 2 * ROWS), th, SMEM_BYTES>>>(
        p_fftA, p_fftA, KFR, KFR / 32,
        p_BrT, p_BrT, KFR, 2 * ROWS,
        p_ct, F2, 2 * ROWS, F2, KFR / 32,
        nullptr, nullptr, nullptr, 0,
        p_ct_h, KD, 0, 0);

    // 2) per-batch constant base
    dim3 bg((F4 + 31) / 32, BSZ);
    k_base<<<bg, th>>>(srcp, tgtp, cw1, cb1, 0);
    k_base<<<bg, th>>>(srcp, tgtp, tw1, tb1, 1028);

    // 3) 20 fixed-point steps
    for (int s = 0; s < MAX_STEPS; s++) {
        // merged freq-net GEMM1: [4096 x 2056]
        k_gemm_h<<<grid(2056, ROWS), th, SMEM_BYTES>>>(
            p_ct_h, p_ct_h + (size_t)ROWS * KD, KD, 17,
            p_w1T, p_w1T, KW1, ROWS,
            p_h, 2056, ROWS, 2056, KW1 / 32,
            nullptr, nullptr, p_base, NBASE,
            nullptr, 0, 0, 1);
        // LN + GELU -> fp16 hidden
        k_ln_gelu<<<dim3(ROWS, 2), th>>>(cg, cbe, tg_, tbe);
        // merged GEMM2: [8192 x 514]
        k_gemm_h<<<grid(F2, 2 * ROWS), th, SMEM_BYTES>>>(
            p_h_h, p_h_h, KW2, KW2 / 32,
            p_cw2T, p_tw2T, KW2, ROWS,
            p_fct, F2, 2 * ROWS, F2, KW2 / 32,
            cb2, tb2, nullptr, 0,
            nullptr, 0, 2, 1);
        // merged gating GEMM: [8192 x 385]
        k_gemm_h<<<grid(NG, 2 * ROWS), th, SMEM_BYTES>>>(
            p_ct_h, p_ct_h, KD, KD / 32,
            p_gwT, p_gwT, KD, 2 * ROWS,
            p_g, 512, 2 * ROWS, NG, KD / 32,
            p_gbias, p_gbias, nullptr, 0,
            nullptr, 0, 1, 1);
        // heads + update fused
        k_gate_update<<<ROWS, th>>>(fd, dw2, db2, sw2, sb2, csc, tsc);
        k_reduce_finalize<<<1, 1024>>>();
        k_apply<<<2 * ROWS, th>>>();
    }

    // 4) irfft: split state, one merged split-fp16 GEMM [8192 x 512 x 1632]
    k_split_state<<<2 * ROWS, th>>>();
    k_gemm_h<<<grid(SPATIAL, 2 * ROWS), th, SMEM_BYTES>>>(
        p_irA, p_irA, KFI, KFI / 32,
        p_BiT, p_BiT, KFI, 2 * ROWS,
        out, SPATIAL, 2 * ROWS, SPATIAL, KFI / 32,
        nullptr, nullptr, nullptr, 0,
        nullptr, 0, 0, 0);
    (void)in_sizes; (void)n_in; (void)out_size;
}

// round 10
// speedup vs baseline: 7.5284x; 1.1452x over previous
#include <cuda_runtime.h>
#include <cuda_fp16.h>
#include <math.h>
#include <stdint.h>

// ---------------- problem constants ----------------
#define BSZ 8
#define SEQ 512
#define ROWS 4096          // BSZ*SEQ
#define SPATIAL 512
#define NF 257             // rfft bins
#define F2 514
#define F4 1028
#define FH 128
#define MAX_STEPS 20
#define TOLV 1e-3f
// padded GEMM dims
#define KW1 1088           // GEMM1 K: 2*544
#define NW1 2176
#define KW2 1056           // GEMM2 K
#define NW2 640
#define KD  544            // gating K / fp16 state row
#define NG  385            // gating N: 257 hd + 128 hs
#define NGP 512
#define NBASE 2176
// FFT split-fp16 GEMM dims
#define KFR 1536           // rfft K: 3*512
#define KFI 1632           // irfft K: 3*544
// GEMM smem: 4 stages x (A 128x40 + B 128x40) halfs
#define STAGE_H 10240
#define STAGE_B 20480
#define SMEM_BYTES (4 * STAGE_B)

// ---------------- device scratch (static, zero-initialized) ----------------
__device__ float g_ct[2 * ROWS * F2];      // fp32 state: rows 0..4095 c, 4096.. t
__device__ float g_new[2 * ROWS * F2];
__device__ float g_h[ROWS * 2056];         // merged GEMM1 output
__device__ float g_fct[2 * ROWS * F2];     // rows 0..4095 fc, 4096.. ft
__device__ float g_g[2 * ROWS * 512];      // gating hidden: cols 0..256 hd, 257..384 hs
__device__ float g_base[BSZ * NBASE];
__device__ float g_gbias[NGP];
__device__ float g_rn_c[ROWS], g_rn_t[ROWS], g_sq_c[ROWS], g_sq_t[ROWS];
__device__ float g_scal[4];
__device__ int   g_done;
// fp16 activations (pads never written -> stay zero)
__device__ __half g_ct_h[2 * ROWS * KD];
__device__ __half g_h_h[2 * ROWS * KW2];
// fp16 K-major weights (pads stay zero)
__device__ __half g_w1T[NW1 * KW1];
__device__ __half g_cw2T[NW2 * KW2];
__device__ __half g_tw2T[NW2 * KW2];
__device__ __half g_gwT[NGP * KD];
// split-fp16 FFT operands/tables
__device__ __half g_fftA[2 * ROWS * KFR];  // [x_hi | x_hi | x_lo]
__device__ __half g_irA[2 * ROWS * KFI];   // [s_hi | s_hi | s_lo]
__device__ __half g_BrT[640 * KFR];        // rfft BT rows: [B_hi | B_lo | B_hi]
__device__ __half g_BiT[512 * KFI];        // irfft BT rows: [B_hi | B_lo | B_hi]

// ---------------- helpers ----------------
__device__ __forceinline__ float gelu_f(float x) {
    return 0.5f * x * (1.0f + erff(x * 0.70710678118654752f));
}
__device__ __forceinline__ uint32_t smem_u32(const void* p) {
    uint32_t a;
    asm("{ .reg .u64 t; cvta.to.shared.u64 t, %1; cvt.u32.u64 %0, t; }" : "=r"(a) : "l"(p));
    return a;
}
__device__ __forceinline__ void cp16(uint32_t dst, const void* src) {
    asm volatile("cp.async.cg.shared.global [%0], [%1], 16;" :: "r"(dst), "l"(src));
}
__device__ __forceinline__ void ldm_x4(uint32_t* r, uint32_t addr) {
    asm volatile("ldmatrix.sync.aligned.m8n8.x4.shared.b16 {%0,%1,%2,%3}, [%4];"
                 : "=r"(r[0]), "=r"(r[1]), "=r"(r[2]), "=r"(r[3]) : "r"(addr));
}

// ---------------- table init: split-fp16 DFT tables ----------------
__global__ void k_init_tables() {
    int idx = blockIdx.x * blockDim.x + threadIdx.x;
    if (idx == 0) g_done = 0;
    int total = SPATIAL * NF;
    if (idx >= total) return;
    int n = idx / NF, q = idx % NF;
    double r = (double)((q * n) & 511) / 256.0;
    double sv, cv;
    sincospi(r, &sv, &cv);
    float cf = (float)cv, sf = (float)(-sv);
    __half chh = __float2half_rn(cf), shh = __float2half_rn(sf);
    __half cll = __float2half_rn(cf - __half2float(chh));
    __half sll = __float2half_rn(sf - __half2float(shh));
    __half* Rc = g_BrT + (size_t)(2 * q) * KFR;
    __half* Rs = g_BrT + (size_t)(2 * q + 1) * KFR;
    Rc[n] = chh; Rc[512 + n] = cll; Rc[1024 + n] = chh;
    Rs[n] = shh; Rs[512 + n] = sll; Rs[1024 + n] = shh;
    double w = (q == 0 || q == NF - 1) ? 1.0 : 2.0;
    float ic = (float)(w * cv / 512.0), is = (float)(-w * sv / 512.0);
    __half ich = __float2half_rn(ic), ish = __float2half_rn(is);
    __half icl = __float2half_rn(ic - __half2float(ich));
    __half isl = __float2half_rn(is - __half2float(ish));
    __half* Bn = g_BiT + (size_t)n * KFI;
    Bn[2 * q] = ich;        Bn[544 + 2 * q] = icl;        Bn[1088 + 2 * q] = ich;
    Bn[2 * q + 1] = ish;    Bn[544 + 2 * q + 1] = isl;    Bn[1088 + 2 * q + 1] = ish;
}

// ---------------- input split: carrier/traj -> [hi|hi|lo] fp16 ----------------
__global__ void k_split_in(const float* __restrict__ carrier, const float* __restrict__ traj) {
    int r = blockIdx.x, tid = threadIdx.x;
    const float* src = (r < ROWS) ? carrier + (size_t)r * SPATIAL
                                  : traj + (size_t)(r - ROWS) * SPATIAL;
    __half* d = g_fftA + (size_t)r * KFR;
    for (int k = tid; k < SPATIAL; k += 256) {
        float x = src[k];
        __half h = __float2half_rn(x);
        __half l = __float2half_rn(x - __half2float(h));
        d[k] = h; d[512 + k] = h; d[1024 + k] = l;
    }
}

// ---------------- state split for irfft ----------------
__global__ void k_split_state() {
    int r = blockIdx.x, tid = threadIdx.x;
    const float* src = g_ct + (size_t)r * F2;
    __half* d = g_irA + (size_t)r * KFI;
    for (int j = tid; j < F2; j += 256) {
        float x = src[j];
        __half h = __float2half_rn(x);
        __half l = __float2half_rn(x - __half2float(h));
        d[j] = h; d[544 + j] = h; d[1088 + j] = l;
    }
}

// ---------------- transpose W[k][n] -> WT[(n_off+n)*ldk + k] fp16 ----------------
__global__ void k_tr(const float* __restrict__ W, int K, int N,
                     __half* __restrict__ WT, int ldk, int n_off) {
    int k = blockIdx.x * 256 + threadIdx.x;
    int n = blockIdx.y;
    if (k >= K) return;
    WT[(size_t)(n_off + n) * ldk + k] = __float2half_rn(W[(size_t)k * N + n]);
}

// ---------------- gating bias concat ----------------
__global__ void k_gbias(const float* __restrict__ db1, const float* __restrict__ sb1) {
    int i = threadIdx.x + blockIdx.x * 256;
    if (i >= NGP) return;
    g_gbias[i] = (i < 257) ? db1[i] : (i < NG ? sb1[i - 257] : 0.f);
}

// =====================================================================
// FP16 tensor GEMM, 4-stage cp.async(16B) pipeline, ldmatrix fragments,
// one sync per K-block, 2 CTAs/SM.
// C = act(A @ BT^T + bias + base); optional fp16 copy Ch.
// =====================================================================
__global__ __launch_bounds__(256, 2) void k_gemm_h(
    const __half* __restrict__ A_lo, const __half* __restrict__ A_hi,
    int ldaH, int kb_lo,
    const __half* __restrict__ B_lo, const __half* __restrict__ B_hi,
    int ldbH, int M_lo,
    float* __restrict__ C, int ldc, int M, int N, int nkb,
    const float* __restrict__ bias_lo, const float* __restrict__ bias_hi,
    const float* __restrict__ base, int base_ld,
    __half* __restrict__ Ch, int ldch,
    int act, int chk) {
    if (chk && g_done) return;
    extern __shared__ __half dyn[];

    const int tid = threadIdx.x;
    const int warp = tid >> 5, lane = tid & 31;
    const int gid = lane >> 2, tg = lane & 3;
    const int wm = warp & 1, wn = warp >> 1;
    const int row0 = blockIdx.y * 128, col0 = blockIdx.x * 128;

    const __half* BT = (row0 < M_lo) ? B_lo : B_hi;
    const float* bias = (row0 < M_lo) ? bias_lo : bias_hi;

    float acc[4][4][4];
#pragma unroll
    for (int mi = 0; mi < 4; mi++)
#pragma unroll
        for (int ni = 0; ni < 4; ni++)
#pragma unroll
            for (int q = 0; q < 4; q++) acc[mi][ni][q] = 0.f;

    const uint32_t sbase = smem_u32(dyn);
    // cp.async coordinates: 64 rows x 4 chunks of 16B per pass, 2 passes
    const int rr2 = tid >> 2;        // 0..63
    const int c16 = tid & 3;         // 16B chunk within 64B row

    auto issue = [&](int kb) {
        int buf = kb & 3;
        const __half* Ab;
        int kk;
        if (kb < kb_lo) { Ab = A_lo; kk = kb * 32; }
        else            { Ab = A_hi; kk = (kb - kb_lo) * 32; }
        uint32_t dA = sbase + buf * STAGE_B + rr2 * 80u + c16 * 16u;
        const __half* gA = Ab + (size_t)(row0 + rr2) * ldaH + kk + c16 * 8;
        cp16(dA, gA);
        cp16(dA + 64 * 80u, gA + (size_t)64 * ldaH);
        uint32_t dB = dA + 10240u;
        const __half* gB = BT + (size_t)(col0 + rr2) * ldbH + kb * 32 + c16 * 8;
        cp16(dB, gB);
        cp16(dB + 64 * 80u, gB + (size_t)64 * ldbH);
        asm volatile("cp.async.commit_group;" ::: "memory");
    };
    auto commit_empty = [&]() {
        asm volatile("cp.async.commit_group;" ::: "memory");
    };

    // ldmatrix lane address components (byte offsets within a stage)
    const uint32_t aRow = (uint32_t)(wm * 64 + (lane & 7) + ((lane & 8) ? 8 : 0));
    const uint32_t aColB = (lane & 16) ? 16u : 0u;
    const uint32_t bRow = (uint32_t)(wn * 32 + (lane & 7) + ((lane & 16) ? 8 : 0));
    const uint32_t bColB = (lane & 8) ? 16u : 0u;

    issue(0);
    if (nkb > 1) issue(1); else commit_empty();

    for (int kb = 0; kb < nkb; kb++) {
        if (kb + 2 < nkb) issue(kb + 2); else commit_empty();
        asm volatile("cp.async.wait_group 2;" ::: "memory");
        __syncthreads();
        int buf = kb & 3;
        uint32_t stA = sbase + buf * STAGE_B;
        uint32_t stB = stA + 10240u;
#pragma unroll
        for (int s = 0; s < 2; s++) {
            uint32_t af[4][4], bf[4][2];
#pragma unroll
            for (int mi = 0; mi < 4; mi++)
                ldm_x4(af[mi], stA + (aRow + mi * 16) * 80u + s * 32u + aColB);
#pragma unroll
            for (int nj = 0; nj < 2; nj++) {
                uint32_t r[4];
                ldm_x4(r, stB + (bRow + nj * 16) * 80u + s * 32u + bColB);
                bf[2 * nj][0] = r[0]; bf[2 * nj][1] = r[1];
                bf[2 * nj + 1][0] = r[2]; bf[2 * nj + 1][1] = r[3];
            }
#pragma unroll
            for (int mi = 0; mi < 4; mi++)
#pragma unroll
                for (int ni = 0; ni < 4; ni++) {
                    asm volatile(
                        "mma.sync.aligned.m16n8k16.row.col.f32.f16.f16.f32 "
                        "{%0,%1,%2,%3}, {%4,%5,%6,%7}, {%8,%9}, {%0,%1,%2,%3};"
                        : "+f"(acc[mi][ni][0]), "+f"(acc[mi][ni][1]),
                          "+f"(acc[mi][ni][2]), "+f"(acc[mi][ni][3])
                        : "r"(af[mi][0]), "r"(af[mi][1]), "r"(af[mi][2]), "r"(af[mi][3]),
                          "r"(bf[ni][0]), "r"(bf[ni][1]));
                }
        }
    }

    // epilogue
#pragma unroll
    for (int mi = 0; mi < 4; mi++) {
#pragma unroll
        for (int ni = 0; ni < 4; ni++) {
#pragma unroll
            for (int q = 0; q < 4; q++) {
                int r = row0 + wm * 64 + mi * 16 + gid + (q >> 1) * 8;
                int c = col0 + wn * 32 + ni * 8 + tg * 2 + (q & 1);
                if (r >= M || c >= N) continue;
                float v = acc[mi][ni][q];
                if (bias) v += bias[c];
                if (base) v += base[(r >> 9) * base_ld + c];
                if (act == 1) v = gelu_f(v);
                else if (act == 2) v = tanhf(v);
                C[(size_t)r * ldc + c] = v;
                if (Ch) Ch[(size_t)r * ldch + c] = __float2half_rn(v);
            }
        }
    }
}

// ---------------- per-batch constant base ----------------
__global__ void k_base(const float* __restrict__ src, const float* __restrict__ tgt,
                       const float* __restrict__ w1, const float* __restrict__ b1,
                       int out_off) {
    int b = blockIdx.y;
    int tid = threadIdx.x;
    int jj = tid & 31;
    int ks = tid >> 5;
    int j = blockIdx.x * 32 + jj;
    float s = 0.f;
    if (j < F4) {
        const float* ps = src + b * 513;
        const float* pt = tgt + b * 513;
        for (int k = ks * 128; k < ks * 128 + 128; k++) {
            float x = (k < 512) ? ps[k] : pt[k - 512];
            s = fmaf(x, w1[(size_t)(F4 + k) * F4 + j], s);
        }
    }
    __shared__ float sh[8][32];
    sh[ks][jj] = s;
    __syncthreads();
    if (ks == 0 && j < F4) {
        float t = b1[j];
#pragma unroll
        for (int q = 0; q < 8; q++) t += sh[q][jj];
        g_base[b * NBASE + out_off + j] = t;
    }
}

// ---------------- LayerNorm + exact GELU -> fp16 hidden ----------------
__global__ void k_ln_gelu(const float* __restrict__ gc, const float* __restrict__ bc,
                          const float* __restrict__ gt, const float* __restrict__ bt) {
    if (g_done) return;
    int r = blockIdx.x, h = blockIdx.y, tid = threadIdx.x;
    const float* g = h ? gt : gc;
    const float* be = h ? bt : bc;
    const float4* hr = (const float4*)(g_h + (size_t)r * 2056 + h * 1028);
    __half2* out = (__half2*)(g_h_h + (size_t)(h * ROWS + r) * KW2);
    float s = 0.f, s2 = 0.f;
    for (int j = tid; j < 257; j += 256) {
        float4 x = hr[j];
        s += x.x + x.y + x.z + x.w;
        s2 += x.x * x.x + x.y * x.y + x.z * x.z + x.w * x.w;
    }
    __shared__ float sa[256], sb[256];
    sa[tid] = s; sb[tid] = s2;
    __syncthreads();
    for (int o = 128; o > 0; o >>= 1) {
        if (tid < o) { sa[tid] += sa[tid + o]; sb[tid] += sb[tid + o]; }
        __syncthreads();
    }
    float mean = sa[0] / F4;
    float var = sb[0] / F4 - mean * mean;
    float rs = rsqrtf(var + 1e-5f);
    const float4* g4 = (const float4*)g;
    const float4* b4 = (const float4*)be;
    for (int j = tid; j < 257; j += 256) {
        float4 x = hr[j], gg = g4[j], bb = b4[j];
        float2 lo, hi;
        lo.x = gelu_f((x.x - mean) * rs * gg.x + bb.x);
        lo.y = gelu_f((x.y - mean) * rs * gg.y + bb.y);
        hi.x = gelu_f((x.z - mean) * rs * gg.z + bb.z);
        hi.y = gelu_f((x.w - mean) * rs * gg.w + bb.w);
        out[2 * j] = __float22half2_rn(lo);
        out[2 * j + 1] = __float22half2_rn(hi);
    }
}

// ---------------- fused heads + update ----------------
__global__ void k_gate_update(const float* __restrict__ fd,
                              const float* __restrict__ dw2, const float* __restrict__ db2,
                              const float* __restrict__ sw2, const float* __restrict__ sb2,
                              const float* __restrict__ cs_p, const float* __restrict__ ts_p) {
    if (g_done) return;
    int row = blockIdx.x, tid = threadIdx.x;
    const float* gc = g_g + (size_t)row * 512;
    const float* gt = g_g + (size_t)(ROWS + row) * 512;
    float s1 = 0.f, s2 = 0.f, s3 = 0.f;
    for (int k = tid; k < 257; k += 256) {
        float w = dw2[k];
        s1 = fmaf(gc[k], w, s1);
        s2 = fmaf(gt[k], w, s2);
    }
    if (tid < 128) s3 = gc[257 + tid] * sw2[tid];
    __shared__ float h1[256], h2[256], h3[256];
    h1[tid] = s1; h2[tid] = s2; h3[tid] = s3;
    __syncthreads();
    for (int o = 128; o > 0; o >>= 1) {
        if (tid < o) { h1[tid] += h1[tid + o]; h2[tid] += h2[tid + o]; h3[tid] += h3[tid + o]; }
        __syncthreads();
    }
    __shared__ float sh_ac, sh_at;
    if (tid == 0) {
        float a_c = 1.f / (1.f + expf(-(h1[0] + db2[0])));
        float a_t = 1.f / (1.f + expf(-(h2[0] + db2[0])));
        if (isnan(a_c)) a_c = 0.f;
        if (isnan(a_t)) a_t = 0.f;
        float gam = 1.f / (1.f + expf(-(h3[0] + sb2[0]))) + 0.5f;
        sh_ac = gam * a_c * (*cs_p);
        sh_at = gam * a_t * (*ts_p);
    }
    __syncthreads();
    float ac = sh_ac, at = sh_at;

    const float2* ct_c = (const float2*)(g_ct + (size_t)row * F2);
    const float2* ct_t = (const float2*)(g_ct + (size_t)(ROWS + row) * F2);
    const float2* fc2 = (const float2*)(g_fct + (size_t)row * F2);
    const float2* ft2 = (const float2*)(g_fct + (size_t)(ROWS + row) * F2);
    float2* nw_c = (float2*)(g_new + (size_t)row * F2);
    float2* nw_t = (float2*)(g_new + (size_t)(ROWS + row) * F2);
    float dc2 = 0.f, dt2 = 0.f, sc2 = 0.f, st2 = 0.f;
    for (int j2 = tid; j2 < 257; j2 += 256) {
        int j = 2 * j2;
        float fd0 = fd[j < NF ? j : j - NF];
        float fd1 = fd[(j + 1) < NF ? (j + 1) : (j + 1 - NF)];
        float2 c = ct_c[j2], f = fc2[j2];
        float2 nc;
        nc.x = fmaf(fd0, c.x, ac * f.x);
        nc.y = fmaf(fd1, c.y, ac * f.y);
        nw_c[j2] = nc;
        float d0 = nc.x - c.x, d1 = nc.y - c.y;
        dc2 += d0 * d0 + d1 * d1; sc2 += nc.x * nc.x + nc.y * nc.y;
        float2 t = ct_t[j2], ff = ft2[j2];
        float2 nt;
        nt.x = fmaf(fd0, t.x, at * ff.x);
        nt.y = fmaf(fd1, t.y, at * ff.y);
        nw_t[j2] = nt;
        d0 = nt.x - t.x; d1 = nt.y - t.y;
        dt2 += d0 * d0 + d1 * d1; st2 += nt.x * nt.x + nt.y * nt.y;
    }
    h1[tid] = dc2; h2[tid] = dt2; h3[tid] = sc2;
    __shared__ float h4[256];
    h4[tid] = st2;
    __syncthreads();
    for (int o = 128; o > 0; o >>= 1) {
        if (tid < o) { h1[tid] += h1[tid + o]; h2[tid] += h2[tid + o];
                       h3[tid] += h3[tid + o]; h4[tid] += h4[tid + o]; }
        __syncthreads();
    }
    if (tid == 0) {
        g_rn_c[row] = sqrtf(h1[0]);
        g_rn_t[row] = sqrtf(h2[0]);
        g_sq_c[row] = h3[0];
        g_sq_t[row] = h4[0];
    }
}

// ---------------- reduce + convergence decision ----------------
__global__ void k_reduce_finalize() {
    __shared__ float4 sh[1024];
    int tid = threadIdx.x;
    float4 a = make_float4(0.f, 0.f, 0.f, 0.f);
    for (int i = tid; i < ROWS; i += 1024) {
        a.x += g_rn_c[i]; a.y += g_rn_t[i]; a.z += g_sq_c[i]; a.w += g_sq_t[i];
    }
    sh[tid] = a;
    __syncthreads();
    for (int o = 512; o > 0; o >>= 1) {
        if (tid < o) {
            sh[tid].x += sh[tid + o].x; sh[tid].y += sh[tid + o].y;
            sh[tid].z += sh[tid + o].z; sh[tid].w += sh[tid + o].w;
        }
        __syncthreads();
    }
    if (tid == 0) {
        if (g_done) {
            g_scal[2] = 0.f;
        } else {
            float dc = sh[0].x / (float)ROWS;
            float dt = sh[0].y / (float)ROWS;
            float nc = sqrtf(sh[0].z);
            float nt = sqrtf(sh[0].w);
            int conv = (dc < TOLV) && (dt < TOLV);
            g_scal[0] = conv ? 1.f : (nc > 10.f ? 10.f / nc : 1.f);
            g_scal[1] = conv ? 1.f : (nt > 10.f ? 10.f / nt : 1.f);
            g_scal[2] = 1.f;
            if (conv) g_done = 1;
        }
    }
}

// ---------------- apply: commit state (fp32 + fp16) ----------------
__global__ void k_apply() {
    if (g_scal[2] == 0.f) return;
    int r = blockIdx.x, tid = threadIdx.x;
    float sc = (r < ROWS) ? g_scal[0] : g_scal[1];
    const float2* nw = (const float2*)(g_new + (size_t)r * F2);
    float2* ct = (float2*)(g_ct + (size_t)r * F2);
    __half2* hh = (__half2*)(g_ct_h + (size_t)r * KD);
    for (int j = tid; j < 257; j += 256) {
        float2 v = nw[j];
        v.x *= sc; v.y *= sc;
        ct[j] = v;
        hh[j] = __float22half2_rn(v);
    }
}

// ---------------- host launch ----------------
extern "C" void kernel_launch(void* const* d_in, const int* in_sizes, int n_in,
                              void* d_out, int out_size) {
    const float* carrier = (const float*)d_in[0];
    const float* traj    = (const float*)d_in[1];
    const float* srcp    = (const float*)d_in[2];
    const float* tgtp    = (const float*)d_in[3];
    const float* cw1 = (const float*)d_in[4];
    const float* cb1 = (const float*)d_in[5];
    const float* cg  = (const float*)d_in[6];
    const float* cbe = (const float*)d_in[7];
    const float* cw2 = (const float*)d_in[8];
    const float* cb2 = (const float*)d_in[9];
    const float* tw1 = (const float*)d_in[10];
    const float* tb1 = (const float*)d_in[11];
    const float* tg_ = (const float*)d_in[12];
    const float* tbe = (const float*)d_in[13];
    const float* tw2 = (const float*)d_in[14];
    const float* tb2 = (const float*)d_in[15];
    const float* fd  = (const float*)d_in[16];
    const float* dw1 = (const float*)d_in[17];
    const float* db1 = (const float*)d_in[18];
    const float* dw2 = (const float*)d_in[19];
    const float* db2 = (const float*)d_in[20];
    const float* sw1 = (const float*)d_in[21];
    const float* sb1 = (const float*)d_in[22];
    const float* sw2 = (const float*)d_in[23];
    const float* sb2 = (const float*)d_in[24];
    const float* csc = (const float*)d_in[25];
    const float* tsc = (const float*)d_in[26];
    float* out = (float*)d_out;

    float *p_ct, *p_h, *p_fct, *p_g, *p_base, *p_gbias;
    __half *p_ct_h, *p_h_h, *p_w1T, *p_cw2T, *p_tw2T, *p_gwT;
    __half *p_fftA, *p_irA, *p_BrT, *p_BiT;
    cudaGetSymbolAddress((void**)&p_ct,   g_ct);
    cudaGetSymbolAddress((void**)&p_h,    g_h);
    cudaGetSymbolAddress((void**)&p_fct,  g_fct);
    cudaGetSymbolAddress((void**)&p_g,    g_g);
    cudaGetSymbolAddress((void**)&p_base, g_base);
    cudaGetSymbolAddress((void**)&p_gbias,g_gbias);
    cudaGetSymbolAddress((void**)&p_ct_h, g_ct_h);
    cudaGetSymbolAddress((void**)&p_h_h,  g_h_h);
    cudaGetSymbolAddress((void**)&p_w1T,  g_w1T);
    cudaGetSymbolAddress((void**)&p_cw2T, g_cw2T);
    cudaGetSymbolAddress((void**)&p_tw2T, g_tw2T);
    cudaGetSymbolAddress((void**)&p_gwT,  g_gwT);
    cudaGetSymbolAddress((void**)&p_fftA, g_fftA);
    cudaGetSymbolAddress((void**)&p_irA,  g_irA);
    cudaGetSymbolAddress((void**)&p_BrT,  g_BrT);
    cudaGetSymbolAddress((void**)&p_BiT,  g_BiT);

    static int s_attr_done = 0;
    if (!s_attr_done) {
        cudaFuncSetAttribute(k_gemm_h, cudaFuncAttributeMaxDynamicSharedMemorySize,
                             SMEM_BYTES);
        s_attr_done = 1;
    }

    dim3 th(256);
    auto grid = [](int N, int M) { return dim3((N + 127) / 128, (M + 127) / 128); };

    // 0) tables + done reset
    k_init_tables<<<(SPATIAL * NF + 255) / 256, 256>>>();

    // 0b) weight transposes (pads stay zero)
    k_tr<<<dim3(3, 1028), th>>>(cw1, 514, F4, p_w1T, KW1, 0);
    k_tr<<<dim3(3, 1028), th>>>(cw1 + (size_t)514 * F4, 514, F4, p_w1T + 544, KW1, 0);
    k_tr<<<dim3(3, 1028), th>>>(tw1, 514, F4, p_w1T, KW1, 1028);
    k_tr<<<dim3(3, 1028), th>>>(tw1 + (size_t)514 * F4, 514, F4, p_w1T + 544, KW1, 1028);
    k_tr<<<dim3(5, 514), th>>>(cw2, F4, F2, p_cw2T, KW2, 0);
    k_tr<<<dim3(5, 514), th>>>(tw2, F4, F2, p_tw2T, KW2, 0);
    k_tr<<<dim3(3, 257), th>>>(dw1, F2, NF, p_gwT, KD, 0);
    k_tr<<<dim3(3, 128), th>>>(sw1, F2, FH, p_gwT, KD, 257);
    k_gbias<<<2, th>>>(db1, sb1);

    // 1) rfft: split inputs, one merged split-fp16 GEMM [8192 x 514 x 1536]
    k_split_in<<<2 * ROWS, th>>>(carrier, traj);
    k_gemm_h<<<grid(F2, 2 * ROWS), th, SMEM_BYTES>>>(
        p_fftA, p_fftA, KFR, KFR / 32,
        p_BrT, p_BrT, KFR, 2 * ROWS,
        p_ct, F2, 2 * ROWS, F2, KFR / 32,
        nullptr, nullptr, nullptr, 0,
        p_ct_h, KD, 0, 0);

    // 2) per-batch constant base
    dim3 bg((F4 + 31) / 32, BSZ);
    k_base<<<bg, th>>>(srcp, tgtp, cw1, cb1, 0);
    k_base<<<bg, th>>>(srcp, tgtp, tw1, tb1, 1028);

    // 3) 20 fixed-point steps
    for (int s = 0; s < MAX_STEPS; s++) {
        // merged freq-net GEMM1: [4096 x 2056]
        k_gemm_h<<<grid(2056, ROWS), th, SMEM_BYTES>>>(
            p_ct_h, p_ct_h + (size_t)ROWS * KD, KD, 17,
            p_w1T, p_w1T, KW1, ROWS,
            p_h, 2056, ROWS, 2056, KW1 / 32,
            nullptr, nullptr, p_base, NBASE,
            nullptr, 0, 0, 1);
        // LN + GELU -> fp16 hidden
        k_ln_gelu<<<dim3(ROWS, 2), th>>>(cg, cbe, tg_, tbe);
        // merged GEMM2: [8192 x 514]
        k_gemm_h<<<grid(F2, 2 * ROWS), th, SMEM_BYTES>>>(
            p_h_h, p_h_h, KW2, KW2 / 32,
            p_cw2T, p_tw2T, KW2, ROWS,
            p_fct, F2, 2 * ROWS, F2, KW2 / 32,
            cb2, tb2, nullptr, 0,
            nullptr, 0, 2, 1);
        // merged gating GEMM: [8192 x 385]
        k_gemm_h<<<grid(NG, 2 * ROWS), th, SMEM_BYTES>>>(
            p_ct_h, p_ct_h, KD, KD / 32,
            p_gwT, p_gwT, KD, 2 * ROWS,
            p_g, 512, 2 * ROWS, NG, KD / 32,
            p_gbias, p_gbias, nullptr, 0,
            nullptr, 0, 1, 1);
        // heads + update fused
        k_gate_update<<<ROWS, th>>>(fd, dw2, db2, sw2, sb2, csc, tsc);
        k_reduce_finalize<<<1, 1024>>>();
        k_apply<<<2 * ROWS, th>>>();
    }

    // 4) irfft: split state, one merged split-fp16 GEMM [8192 x 512 x 1632]
    k_split_state<<<2 * ROWS, th>>>();
    k_gemm_h<<<grid(SPATIAL, 2 * ROWS), th, SMEM_BYTES>>>(
        p_irA, p_irA, KFI, KFI / 32,
        p_BiT, p_BiT, KFI, 2 * ROWS,
        out, SPATIAL, 2 * ROWS, SPATIAL, KFI / 32,
        nullptr, nullptr, nullptr, 0,
        nullptr, 0, 0, 0);
    (void)in_sizes; (void)n_in; (void)out_size;
}